// round 2
// baseline (speedup 1.0000x reference)
#include <cuda_runtime.h>

// Problem constants
#define BB 4
#define SS 8192
#define DD 512
#define HH 8
#define DHD 64
#define MR (BB*SS)          // 32768 rows
#define EPSF 1e-6f
#define KVC 32              // s-chunks for kv reduction

// Output layout (concatenated tuple): out [B,S,D], k_v [B,H,DH,DH], z [B,H,DH]
#define OFF_KV ((size_t)MR*DD)                     // 16777216
#define NKV (BB*HH*DHD*DHD)                        // 131072
#define OFF_Z (OFF_KV + NKV)                       // 16908288
#define NZ (BB*HH*DHD)                             // 2048

// Scratch (device globals; no allocations allowed)
__device__ float g_Q[(size_t)MR*DD];
__device__ float g_K[(size_t)MR*DD];
__device__ float g_V[(size_t)MR*DD];
__device__ float g_att[(size_t)MR*DD];
__device__ float g_kv_part[(size_t)KVC*BB*HH*DHD*DHD];
__device__ float g_z_part[(size_t)KVC*BB*HH*DHD];
__device__ float g_kv[NKV];
__device__ float g_z[NZ];

// ---------------------------------------------------------------------------
// GEMM: C[M,512] = A[M,512] @ W[512,512]^T + bias, optional (elu(x)+1)
// 128x128 tile, BK=16, 256 threads, 8x8 per thread
// ---------------------------------------------------------------------------
__global__ void __launch_bounds__(256)
gemm_xwt_kernel(const float* __restrict__ A, const float* __restrict__ W,
                const float* __restrict__ bias, float* __restrict__ C, int act)
{
    __shared__ float As[16][128];
    __shared__ float Ws[16][128];

    const int tid = threadIdx.x;
    const int tx = tid & 15;
    const int ty = tid >> 4;
    const int m0 = blockIdx.y * 128;
    const int n0 = blockIdx.x * 128;

    float acc[8][8];
#pragma unroll
    for (int i = 0; i < 8; i++)
#pragma unroll
        for (int j = 0; j < 8; j++) acc[i][j] = 0.f;

    const int lrow = tid >> 1;        // 0..127
    const int lk8  = (tid & 1) * 8;   // 0 or 8 (float column within BK=16)

    const float* Arow = A + (size_t)(m0 + lrow) * DD + lk8;
    const float* Wrow = W + (size_t)(n0 + lrow) * DD + lk8;

    for (int kt = 0; kt < DD; kt += 16) {
        float4 a0 = *(const float4*)(Arow + kt);
        float4 a1 = *(const float4*)(Arow + kt + 4);
        float4 w0 = *(const float4*)(Wrow + kt);
        float4 w1 = *(const float4*)(Wrow + kt + 4);

        As[lk8 + 0][lrow] = a0.x; As[lk8 + 1][lrow] = a0.y;
        As[lk8 + 2][lrow] = a0.z; As[lk8 + 3][lrow] = a0.w;
        As[lk8 + 4][lrow] = a1.x; As[lk8 + 5][lrow] = a1.y;
        As[lk8 + 6][lrow] = a1.z; As[lk8 + 7][lrow] = a1.w;
        Ws[lk8 + 0][lrow] = w0.x; Ws[lk8 + 1][lrow] = w0.y;
        Ws[lk8 + 2][lrow] = w0.z; Ws[lk8 + 3][lrow] = w0.w;
        Ws[lk8 + 4][lrow] = w1.x; Ws[lk8 + 5][lrow] = w1.y;
        Ws[lk8 + 6][lrow] = w1.z; Ws[lk8 + 7][lrow] = w1.w;
        __syncthreads();

#pragma unroll
        for (int k = 0; k < 16; k++) {
            float4 af0 = *(const float4*)&As[k][ty * 8];
            float4 af1 = *(const float4*)&As[k][ty * 8 + 4];
            float4 bf0 = *(const float4*)&Ws[k][tx * 8];
            float4 bf1 = *(const float4*)&Ws[k][tx * 8 + 4];
            float a[8] = {af0.x, af0.y, af0.z, af0.w, af1.x, af1.y, af1.z, af1.w};
            float b[8] = {bf0.x, bf0.y, bf0.z, bf0.w, bf1.x, bf1.y, bf1.z, bf1.w};
#pragma unroll
            for (int i = 0; i < 8; i++)
#pragma unroll
                for (int j = 0; j < 8; j++)
                    acc[i][j] = fmaf(a[i], b[j], acc[i][j]);
        }
        __syncthreads();
    }

    // epilogue
    float bv[8];
#pragma unroll
    for (int j = 0; j < 8; j++) bv[j] = bias[n0 + tx * 8 + j];

#pragma unroll
    for (int i = 0; i < 8; i++) {
        const int row = m0 + ty * 8 + i;
        float v[8];
#pragma unroll
        for (int j = 0; j < 8; j++) {
            float x = acc[i][j] + bv[j];
            if (act) x = (x > 0.f) ? (x + 1.f) : __expf(x);  // elu(x)+1
            v[j] = x;
        }
        float* Crow = C + (size_t)row * DD + n0 + tx * 8;
        *(float4*)(Crow)     = make_float4(v[0], v[1], v[2], v[3]);
        *(float4*)(Crow + 4) = make_float4(v[4], v[5], v[6], v[7]);
    }
}

// ---------------------------------------------------------------------------
// KV reduce: per (b,h,chunk), partial kv[d][m] = sum_s K[s][d]*V[s][m],
//            partial z[d] = sum_s K[s][d]
// ---------------------------------------------------------------------------
__global__ void __launch_bounds__(256)
kv_reduce_kernel(const float* __restrict__ Kmat, const float* __restrict__ Vmat)
{
    const int bh = blockIdx.x;       // 0..31
    const int chunk = blockIdx.y;    // 0..KVC-1
    const int b = bh / HH, h = bh % HH;
    const int s_begin = chunk * (SS / KVC);  // 256 rows per chunk

    const float* Kbase = Kmat + (size_t)b * SS * DD + h * DHD;
    const float* Vbase = Vmat + (size_t)b * SS * DD + h * DHD;

    __shared__ float Ks[16][DHD];
    __shared__ float Vs[16][DHD];

    const int tid = threadIdx.x;
    const int tx = tid & 15;
    const int ty = tid >> 4;
    const int lr = tid >> 4;     // 0..15 row for loading
    const int lc = (tid & 15) * 4;

    float acc[4][4];
#pragma unroll
    for (int i = 0; i < 4; i++)
#pragma unroll
        for (int j = 0; j < 4; j++) acc[i][j] = 0.f;
    float zacc = 0.f;

    for (int s0 = 0; s0 < SS / KVC; s0 += 16) {
        const int srow = s_begin + s0 + lr;
        float4 kk = *(const float4*)(Kbase + (size_t)srow * DD + lc);
        float4 vv = *(const float4*)(Vbase + (size_t)srow * DD + lc);
        *(float4*)&Ks[lr][lc] = kk;
        *(float4*)&Vs[lr][lc] = vv;
        __syncthreads();

#pragma unroll
        for (int ss = 0; ss < 16; ss++) {
            float4 a4 = *(const float4*)&Ks[ss][ty * 4];
            float4 b4 = *(const float4*)&Vs[ss][tx * 4];
            float a[4] = {a4.x, a4.y, a4.z, a4.w};
            float bb[4] = {b4.x, b4.y, b4.z, b4.w};
#pragma unroll
            for (int i = 0; i < 4; i++)
#pragma unroll
                for (int j = 0; j < 4; j++)
                    acc[i][j] = fmaf(a[i], bb[j], acc[i][j]);
        }
        if (tid < DHD) {
#pragma unroll
            for (int ss = 0; ss < 16; ss++) zacc += Ks[ss][tid];
        }
        __syncthreads();
    }

    float* kvp = g_kv_part + ((size_t)chunk * (BB * HH) + bh) * DHD * DHD;
#pragma unroll
    for (int i = 0; i < 4; i++) {
        const int d = ty * 4 + i;
        *(float4*)&kvp[d * DHD + tx * 4] = make_float4(acc[i][0], acc[i][1], acc[i][2], acc[i][3]);
    }
    if (tid < DHD)
        g_z_part[((size_t)chunk * (BB * HH) + bh) * DHD + tid] = zacc;
}

// ---------------------------------------------------------------------------
// Finalize: sum partials deterministically -> g_kv / g_z (+ optional d_out copy)
// ---------------------------------------------------------------------------
__global__ void __launch_bounds__(256)
kv_finalize_kernel(float* __restrict__ dout, int write_out)
{
    const int idx = blockIdx.x * blockDim.x + threadIdx.x;
    if (idx < NKV) {
        float s = 0.f;
#pragma unroll
        for (int c = 0; c < KVC; c++) s += g_kv_part[(size_t)c * NKV + idx];
        g_kv[idx] = s;
        if (write_out) dout[OFF_KV + idx] = s;
    } else if (idx < NKV + NZ) {
        const int id2 = idx - NKV;
        float s = 0.f;
#pragma unroll
        for (int c = 0; c < KVC; c++) s += g_z_part[(size_t)c * NZ + id2];
        g_z[id2] = s;
        if (write_out) dout[OFF_Z + id2] = s;
    }
}

// ---------------------------------------------------------------------------
// Attention apply: att[s][m] = (sum_d Q[s][d]*kv[d][m]) / (sum_d Q[s][d]*z[d] + eps)
// One block per (b,h, 128-row chunk); kv tile resident in smem.
// ---------------------------------------------------------------------------
__global__ void __launch_bounds__(256)
attn_apply_kernel(const float* __restrict__ Q)
{
    const int bh = blockIdx.x;
    const int chunk = blockIdx.y;     // 64 chunks of 128 rows
    const int b = bh / HH, h = bh % HH;

    __shared__ float kvs[DHD][DHD];   // 16 KB
    __shared__ float zs[DHD];
    __shared__ float Qs[16][DHD];

    const int tid = threadIdx.x;
    const int tx = tid & 15;          // 4 output cols each
    const int ty = tid >> 4;          // row within 16-row group

    const float* kvsrc = g_kv + (size_t)bh * DHD * DHD;
    // 4096 floats = 1024 float4, 256 threads -> 4 each
#pragma unroll
    for (int t = 0; t < 4; t++) {
        const int f4 = tid * 4 + t;       // float4 index
        const int d = f4 >> 4;            // row (16 float4 per row)
        const int c = (f4 & 15) * 4;
        *(float4*)&kvs[d][c] = *(const float4*)(kvsrc + d * DHD + c);
    }
    if (tid < DHD) zs[tid] = g_z[(size_t)bh * DHD + tid];
    __syncthreads();

    const float* Qbase = Q + (size_t)b * SS * DD + h * DHD;
    float* Obase = g_att + (size_t)b * SS * DD + h * DHD;
    const int row0 = chunk * 128;

    for (int g = 0; g < 8; g++) {
        const int lr = tid >> 4;
        const int lc = (tid & 15) * 4;
        const int srow = row0 + g * 16 + lr;
        *(float4*)&Qs[lr][lc] = *(const float4*)(Qbase + (size_t)srow * DD + lc);
        __syncthreads();

        float num[4] = {0.f, 0.f, 0.f, 0.f};
        float den = 0.f;
#pragma unroll
        for (int d = 0; d < DHD; d++) {
            const float qd = Qs[ty][d];
            float4 kvv = *(const float4*)&kvs[d][tx * 4];
            num[0] = fmaf(qd, kvv.x, num[0]);
            num[1] = fmaf(qd, kvv.y, num[1]);
            num[2] = fmaf(qd, kvv.z, num[2]);
            num[3] = fmaf(qd, kvv.w, num[3]);
            den = fmaf(qd, zs[d], den);
        }
        const float inv = 1.0f / (den + EPSF);
        const int orow = row0 + g * 16 + ty;
        *(float4*)(Obase + (size_t)orow * DD + tx * 4) =
            make_float4(num[0] * inv, num[1] * inv, num[2] * inv, num[3] * inv);
        __syncthreads();
    }
}

// ---------------------------------------------------------------------------
// Launch
// ---------------------------------------------------------------------------
extern "C" void kernel_launch(void* const* d_in, const int* in_sizes, int n_in,
                              void* d_out, int out_size)
{
    const float* q  = (const float*)d_in[0];
    const float* k  = (const float*)d_in[1];
    const float* v  = (const float*)d_in[2];
    const float* Wq = (const float*)d_in[3];
    const float* bq = (const float*)d_in[4];
    const float* Wk = (const float*)d_in[5];
    const float* bk = (const float*)d_in[6];
    const float* Wv = (const float*)d_in[7];
    const float* bv = (const float*)d_in[8];
    const float* Wo = (const float*)d_in[9];
    const float* bo = (const float*)d_in[10];
    float* out = (float*)d_out;

    float *gQ, *gK, *gV, *gA;
    cudaGetSymbolAddress((void**)&gQ, g_Q);
    cudaGetSymbolAddress((void**)&gK, g_K);
    cudaGetSymbolAddress((void**)&gV, g_V);
    cudaGetSymbolAddress((void**)&gA, g_att);

    const int write_extra = ((size_t)out_size >= OFF_Z + NZ) ? 1 : 0;

    dim3 gemm_grid(DD / 128, MR / 128);   // (4, 256)
    gemm_xwt_kernel<<<gemm_grid, 256>>>(q, Wq, bq, gQ, 1);
    gemm_xwt_kernel<<<gemm_grid, 256>>>(k, Wk, bk, gK, 1);
    gemm_xwt_kernel<<<gemm_grid, 256>>>(v, Wv, bv, gV, 0);

    dim3 kv_grid(BB * HH, KVC);           // (32, 32)
    kv_reduce_kernel<<<kv_grid, 256>>>(gK, gV);

    const int fin_total = NKV + NZ;
    kv_finalize_kernel<<<(fin_total + 255) / 256, 256>>>(out, write_extra);

    dim3 att_grid(BB * HH, SS / 128);     // (32, 64)
    attn_apply_kernel<<<att_grid, 256>>>(gQ);

    gemm_xwt_kernel<<<gemm_grid, 256>>>(gA, Wo, bo, out, 0);
}

// round 3
// speedup vs baseline: 2.2122x; 2.2122x over previous
#include <cuda_runtime.h>
#include <cstdint>

// Problem constants
#define BB 4
#define SS 8192
#define DD 512
#define HH 8
#define DHD 64
#define MR (BB*SS)          // 32768 rows
#define EPSF 1e-6f
#define KVC 32              // s-chunks for kv reduction

// Output layout (concatenated tuple): out [B,S,D], k_v [B,H,DH,DH], z [B,H,DH]
#define OFF_KV ((size_t)MR*DD)                     // 16777216
#define NKV (BB*HH*DHD*DHD)                        // 131072
#define OFF_Z (OFF_KV + NKV)                       // 16908288
#define NZ (BB*HH*DHD)                             // 2048

// Scratch (device globals; no allocations allowed)
__device__ float g_Q[(size_t)MR*DD];
__device__ float g_K[(size_t)MR*DD];
__device__ float g_V[(size_t)MR*DD];
__device__ float g_att[(size_t)MR*DD];
__device__ float g_kv_part[(size_t)KVC*BB*HH*DHD*DHD];
__device__ float g_z_part[(size_t)KVC*BB*HH*DHD];
__device__ float g_kv[NKV];
__device__ float g_z[NZ];

__device__ __forceinline__ uint32_t f2tf(float x) {
    uint32_t r;
    asm("cvt.rna.tf32.f32 %0, %1;" : "=r"(r) : "f"(x));
    return r;
}

// ---------------------------------------------------------------------------
// tf32 tensor-core GEMM: C[M,512] = A[M,512] @ W[512,512]^T + bias, opt elu+1
// BM=128, BN=256, BK=16, 256 threads (8 warps, 2x4), warp tile 64x64.
// Smem rows padded to 20 floats -> conflict-free mma fragment loads.
// Register-staged double-buffered pipeline, 1 syncthreads per K-iter.
// ---------------------------------------------------------------------------
#define GPAD 20
#define GSTAGE ((128 + 256) * GPAD)   // u32 per stage = 7680

__global__ void __launch_bounds__(256, 1)
gemm_tf32_kernel(const float* __restrict__ A, const float* __restrict__ W,
                 const float* __restrict__ bias, float* __restrict__ C, int act)
{
    extern __shared__ uint32_t smg[];

    const int tid  = threadIdx.x;
    const int lane = tid & 31;
    const int wid  = tid >> 5;
    const int wm   = wid & 1;        // 2 warp rows
    const int wn   = wid >> 1;       // 4 warp cols
    const int g    = lane >> 2;      // 0..7
    const int tq   = lane & 3;       // 0..3
    const int m0   = blockIdx.y * 128;
    const int n0   = blockIdx.x * 256;

    float acc[4][8][4];
#pragma unroll
    for (int i = 0; i < 4; i++)
#pragma unroll
        for (int j = 0; j < 8; j++)
#pragma unroll
            for (int c = 0; c < 4; c++) acc[i][j][c] = 0.f;

    // Global-load assignments (float4 granules)
    int arow[2], aco[2], brow[4], bco[4];
#pragma unroll
    for (int j = 0; j < 2; j++) { int id = tid + 256 * j; arow[j] = id >> 2; aco[j] = (id & 3) * 4; }
#pragma unroll
    for (int j = 0; j < 4; j++) { int id = tid + 256 * j; brow[j] = id >> 2; bco[j] = (id & 3) * 4; }

    const float* Ag = A + (size_t)m0 * DD;
    const float* Wg = W + (size_t)n0 * DD;

    float4 la[2], lb[4];

    // Prologue: load k-tile 0 and stage into buffer 0
#pragma unroll
    for (int j = 0; j < 2; j++) la[j] = *(const float4*)(Ag + (size_t)arow[j] * DD + aco[j]);
#pragma unroll
    for (int j = 0; j < 4; j++) lb[j] = *(const float4*)(Wg + (size_t)brow[j] * DD + bco[j]);
    {
        uint32_t* sA = smg;
        uint32_t* sB = smg + 128 * GPAD;
#pragma unroll
        for (int j = 0; j < 2; j++) {
            uint32_t* p = sA + arow[j] * GPAD + aco[j];
            p[0] = f2tf(la[j].x); p[1] = f2tf(la[j].y); p[2] = f2tf(la[j].z); p[3] = f2tf(la[j].w);
        }
#pragma unroll
        for (int j = 0; j < 4; j++) {
            uint32_t* p = sB + brow[j] * GPAD + bco[j];
            p[0] = f2tf(lb[j].x); p[1] = f2tf(lb[j].y); p[2] = f2tf(lb[j].z); p[3] = f2tf(lb[j].w);
        }
    }
    __syncthreads();

    for (int kt = 0; kt < 32; kt++) {
        // Prefetch next k-tile from global while computing current
        if (kt < 31) {
            const int kk = (kt + 1) * 16;
#pragma unroll
            for (int j = 0; j < 2; j++)
                la[j] = *(const float4*)(Ag + (size_t)arow[j] * DD + kk + aco[j]);
#pragma unroll
            for (int j = 0; j < 4; j++)
                lb[j] = *(const float4*)(Wg + (size_t)brow[j] * DD + kk + bco[j]);
        }

        const uint32_t* sA = smg + (kt & 1) * GSTAGE;
        const uint32_t* sB = sA + 128 * GPAD;

#pragma unroll
        for (int ks = 0; ks < 16; ks += 8) {
            uint32_t af[4][4], bf[8][2];
#pragma unroll
            for (int mi = 0; mi < 4; mi++) {
                const int r = wm * 64 + mi * 16 + g;
                af[mi][0] = sA[r * GPAD + ks + tq];
                af[mi][1] = sA[(r + 8) * GPAD + ks + tq];
                af[mi][2] = sA[r * GPAD + ks + tq + 4];
                af[mi][3] = sA[(r + 8) * GPAD + ks + tq + 4];
            }
#pragma unroll
            for (int ni = 0; ni < 8; ni++) {
                const int r = wn * 64 + ni * 8 + g;
                bf[ni][0] = sB[r * GPAD + ks + tq];
                bf[ni][1] = sB[r * GPAD + ks + tq + 4];
            }
#pragma unroll
            for (int mi = 0; mi < 4; mi++)
#pragma unroll
                for (int ni = 0; ni < 8; ni++) {
                    asm volatile(
                        "mma.sync.aligned.m16n8k8.row.col.f32.tf32.tf32.f32 "
                        "{%0,%1,%2,%3}, {%4,%5,%6,%7}, {%8,%9}, {%0,%1,%2,%3};\n"
                        : "+f"(acc[mi][ni][0]), "+f"(acc[mi][ni][1]),
                          "+f"(acc[mi][ni][2]), "+f"(acc[mi][ni][3])
                        : "r"(af[mi][0]), "r"(af[mi][1]), "r"(af[mi][2]), "r"(af[mi][3]),
                          "r"(bf[ni][0]), "r"(bf[ni][1]));
                }
        }

        if (kt < 31) {
            uint32_t* dA = smg + ((kt + 1) & 1) * GSTAGE;
            uint32_t* dB = dA + 128 * GPAD;
#pragma unroll
            for (int j = 0; j < 2; j++) {
                uint32_t* p = dA + arow[j] * GPAD + aco[j];
                p[0] = f2tf(la[j].x); p[1] = f2tf(la[j].y); p[2] = f2tf(la[j].z); p[3] = f2tf(la[j].w);
            }
#pragma unroll
            for (int j = 0; j < 4; j++) {
                uint32_t* p = dB + brow[j] * GPAD + bco[j];
                p[0] = f2tf(lb[j].x); p[1] = f2tf(lb[j].y); p[2] = f2tf(lb[j].z); p[3] = f2tf(lb[j].w);
            }
        }
        __syncthreads();
    }

    // Epilogue: bias + optional elu(x)+1, write fp32
#pragma unroll
    for (int mi = 0; mi < 4; mi++) {
        const int row = m0 + wm * 64 + mi * 16 + g;
#pragma unroll
        for (int ni = 0; ni < 8; ni++) {
            const int col = n0 + wn * 64 + ni * 8 + tq * 2;
            const float b0 = bias[col], b1 = bias[col + 1];
            float v0 = acc[mi][ni][0] + b0;
            float v1 = acc[mi][ni][1] + b1;
            float v2 = acc[mi][ni][2] + b0;
            float v3 = acc[mi][ni][3] + b1;
            if (act) {
                v0 = (v0 > 0.f) ? (v0 + 1.f) : __expf(v0);
                v1 = (v1 > 0.f) ? (v1 + 1.f) : __expf(v1);
                v2 = (v2 > 0.f) ? (v2 + 1.f) : __expf(v2);
                v3 = (v3 > 0.f) ? (v3 + 1.f) : __expf(v3);
            }
            *(float2*)(C + (size_t)row * DD + col)       = make_float2(v0, v1);
            *(float2*)(C + (size_t)(row + 8) * DD + col) = make_float2(v2, v3);
        }
    }
}

// ---------------------------------------------------------------------------
// KV reduce: per (b,h,chunk), partial kv[d][m] = sum_s K[s][d]*V[s][m],
//            partial z[d] = sum_s K[s][d]
// ---------------------------------------------------------------------------
__global__ void __launch_bounds__(256)
kv_reduce_kernel(const float* __restrict__ Kmat, const float* __restrict__ Vmat)
{
    const int bh = blockIdx.x;       // 0..31
    const int chunk = blockIdx.y;    // 0..KVC-1
    const int b = bh / HH, h = bh % HH;
    const int s_begin = chunk * (SS / KVC);  // 256 rows per chunk

    const float* Kbase = Kmat + (size_t)b * SS * DD + h * DHD;
    const float* Vbase = Vmat + (size_t)b * SS * DD + h * DHD;

    __shared__ float Ks[16][DHD];
    __shared__ float Vs[16][DHD];

    const int tid = threadIdx.x;
    const int tx = tid & 15;
    const int ty = tid >> 4;
    const int lr = tid >> 4;     // 0..15 row for loading
    const int lc = (tid & 15) * 4;

    float acc[4][4];
#pragma unroll
    for (int i = 0; i < 4; i++)
#pragma unroll
        for (int j = 0; j < 4; j++) acc[i][j] = 0.f;
    float zacc = 0.f;

    for (int s0 = 0; s0 < SS / KVC; s0 += 16) {
        const int srow = s_begin + s0 + lr;
        float4 kk = *(const float4*)(Kbase + (size_t)srow * DD + lc);
        float4 vv = *(const float4*)(Vbase + (size_t)srow * DD + lc);
        *(float4*)&Ks[lr][lc] = kk;
        *(float4*)&Vs[lr][lc] = vv;
        __syncthreads();

#pragma unroll
        for (int ss = 0; ss < 16; ss++) {
            float4 a4 = *(const float4*)&Ks[ss][ty * 4];
            float4 b4 = *(const float4*)&Vs[ss][tx * 4];
            float a[4] = {a4.x, a4.y, a4.z, a4.w};
            float bb[4] = {b4.x, b4.y, b4.z, b4.w};
#pragma unroll
            for (int i = 0; i < 4; i++)
#pragma unroll
                for (int j = 0; j < 4; j++)
                    acc[i][j] = fmaf(a[i], bb[j], acc[i][j]);
        }
        if (tid < DHD) {
#pragma unroll
            for (int ss = 0; ss < 16; ss++) zacc += Ks[ss][tid];
        }
        __syncthreads();
    }

    float* kvp = g_kv_part + ((size_t)chunk * (BB * HH) + bh) * DHD * DHD;
#pragma unroll
    for (int i = 0; i < 4; i++) {
        const int d = ty * 4 + i;
        *(float4*)&kvp[d * DHD + tx * 4] = make_float4(acc[i][0], acc[i][1], acc[i][2], acc[i][3]);
    }
    if (tid < DHD)
        g_z_part[((size_t)chunk * (BB * HH) + bh) * DHD + tid] = zacc;
}

// ---------------------------------------------------------------------------
// Finalize: sum partials deterministically -> g_kv / g_z (+ optional d_out copy)
// ---------------------------------------------------------------------------
__global__ void __launch_bounds__(256)
kv_finalize_kernel(float* __restrict__ dout, int write_out)
{
    const int idx = blockIdx.x * blockDim.x + threadIdx.x;
    if (idx < NKV) {
        float s = 0.f;
#pragma unroll
        for (int c = 0; c < KVC; c++) s += g_kv_part[(size_t)c * NKV + idx];
        g_kv[idx] = s;
        if (write_out) dout[OFF_KV + idx] = s;
    } else if (idx < NKV + NZ) {
        const int id2 = idx - NKV;
        float s = 0.f;
#pragma unroll
        for (int c = 0; c < KVC; c++) s += g_z_part[(size_t)c * NZ + id2];
        g_z[id2] = s;
        if (write_out) dout[OFF_Z + id2] = s;
    }
}

// ---------------------------------------------------------------------------
// Attention apply: att[s][m] = (sum_d Q[s][d]*kv[d][m]) / (sum_d Q[s][d]*z[d] + eps)
// ---------------------------------------------------------------------------
__global__ void __launch_bounds__(256)
attn_apply_kernel(const float* __restrict__ Q)
{
    const int bh = blockIdx.x;
    const int chunk = blockIdx.y;     // 64 chunks of 128 rows
    const int b = bh / HH, h = bh % HH;

    __shared__ float kvs[DHD][DHD];   // 16 KB
    __shared__ float zs[DHD];
    __shared__ float Qs[16][DHD];

    const int tid = threadIdx.x;
    const int tx = tid & 15;          // 4 output cols each
    const int ty = tid >> 4;          // row within 16-row group

    const float* kvsrc = g_kv + (size_t)bh * DHD * DHD;
#pragma unroll
    for (int t = 0; t < 4; t++) {
        const int f4 = tid * 4 + t;
        const int d = f4 >> 4;
        const int c = (f4 & 15) * 4;
        *(float4*)&kvs[d][c] = *(const float4*)(kvsrc + d * DHD + c);
    }
    if (tid < DHD) zs[tid] = g_z[(size_t)bh * DHD + tid];
    __syncthreads();

    const float* Qbase = Q + (size_t)b * SS * DD + h * DHD;
    float* Obase = g_att + (size_t)b * SS * DD + h * DHD;
    const int row0 = chunk * 128;

    for (int gi = 0; gi < 8; gi++) {
        const int lr = tid >> 4;
        const int lc = (tid & 15) * 4;
        const int srow = row0 + gi * 16 + lr;
        *(float4*)&Qs[lr][lc] = *(const float4*)(Qbase + (size_t)srow * DD + lc);
        __syncthreads();

        float num[4] = {0.f, 0.f, 0.f, 0.f};
        float den = 0.f;
#pragma unroll
        for (int d = 0; d < DHD; d++) {
            const float qd = Qs[ty][d];
            float4 kvv = *(const float4*)&kvs[d][tx * 4];
            num[0] = fmaf(qd, kvv.x, num[0]);
            num[1] = fmaf(qd, kvv.y, num[1]);
            num[2] = fmaf(qd, kvv.z, num[2]);
            num[3] = fmaf(qd, kvv.w, num[3]);
            den = fmaf(qd, zs[d], den);
        }
        const float inv = 1.0f / (den + EPSF);
        const int orow = row0 + gi * 16 + ty;
        *(float4*)(Obase + (size_t)orow * DD + tx * 4) =
            make_float4(num[0] * inv, num[1] * inv, num[2] * inv, num[3] * inv);
        __syncthreads();
    }
}

// ---------------------------------------------------------------------------
// Launch
// ---------------------------------------------------------------------------
extern "C" void kernel_launch(void* const* d_in, const int* in_sizes, int n_in,
                              void* d_out, int out_size)
{
    const float* q  = (const float*)d_in[0];
    const float* k  = (const float*)d_in[1];
    const float* v  = (const float*)d_in[2];
    const float* Wq = (const float*)d_in[3];
    const float* bq = (const float*)d_in[4];
    const float* Wk = (const float*)d_in[5];
    const float* bk = (const float*)d_in[6];
    const float* Wv = (const float*)d_in[7];
    const float* bv = (const float*)d_in[8];
    const float* Wo = (const float*)d_in[9];
    const float* bo = (const float*)d_in[10];
    float* out = (float*)d_out;

    float *gQ, *gK, *gV, *gA;
    cudaGetSymbolAddress((void**)&gQ, g_Q);
    cudaGetSymbolAddress((void**)&gK, g_K);
    cudaGetSymbolAddress((void**)&gV, g_V);
    cudaGetSymbolAddress((void**)&gA, g_att);

    const int write_extra = ((size_t)out_size >= OFF_Z + NZ) ? 1 : 0;

    const int gemm_smem = 2 * GSTAGE * 4;   // 61440 bytes
    cudaFuncSetAttribute(gemm_tf32_kernel,
                         cudaFuncAttributeMaxDynamicSharedMemorySize, gemm_smem);

    dim3 gemm_grid(DD / 256, MR / 128);     // (2, 256)
    gemm_tf32_kernel<<<gemm_grid, 256, gemm_smem>>>(q, Wq, bq, gQ, 1);
    gemm_tf32_kernel<<<gemm_grid, 256, gemm_smem>>>(k, Wk, bk, gK, 1);
    gemm_tf32_kernel<<<gemm_grid, 256, gemm_smem>>>(v, Wv, bv, gV, 0);

    dim3 kv_grid(BB * HH, KVC);             // (32, 32)
    kv_reduce_kernel<<<kv_grid, 256>>>(gK, gV);

    const int fin_total = NKV + NZ;
    kv_finalize_kernel<<<(fin_total + 255) / 256, 256>>>(out, write_extra);

    dim3 att_grid(BB * HH, SS / 128);       // (32, 64)
    attn_apply_kernel<<<att_grid, 256>>>(gQ);

    gemm_tf32_kernel<<<gemm_grid, 256, gemm_smem>>>(gA, Wo, bo, out, 0);
}

// round 6
// speedup vs baseline: 3.3570x; 1.5175x over previous
#include <cuda_runtime.h>
#include <cuda_fp16.h>
#include <cstdint>

// Problem constants
#define BB 4
#define SS 8192
#define DD 512
#define HH 8
#define DHD 64
#define MR (BB*SS)          // 32768 rows
#define EPSF 1e-6f
#define KVC 32              // s-chunks for kv reduction

// Output layout (concatenated tuple): out [B,S,D], k_v [B,H,DH,DH], z [B,H,DH]
#define OFF_KV ((size_t)MR*DD)                     // 16777216
#define NKV (BB*HH*DHD*DHD)                        // 131072
#define OFF_Z (OFF_KV + NKV)                       // 16908288
#define NZ (BB*HH*DHD)                             // 2048

// Scratch (device globals; no allocations allowed)
__device__ float g_Q[(size_t)MR*DD];
__device__ float g_K[(size_t)MR*DD];
__device__ float g_V[(size_t)MR*DD];
__device__ float g_kv_part[(size_t)KVC*BB*HH*DHD*DHD];
__device__ float g_z_part[(size_t)KVC*BB*HH*DHD];
__device__ __half g_kvT[NKV];   // transposed [b,h,m,d] fp16 for fused out-GEMM
__device__ float g_z[NZ];

// ===========================================================================
// fp16 tensor-core GEMM: C[M,512] = A[M,512] @ W[512,512]^T + bias, opt elu+1
// BM=128, BN=256, BK=16, 256 threads (8 warps 2x4), warp tile 64x64.
// fp16 operands (11-bit significand ~ tf32), fp32 accumulate.
// Smem rows padded to 24 halves -> conflict-free LDS.32 fragment loads.
// Register-staged double-buffered pipeline, 1 sync per K-iter.
// ===========================================================================
#define PADH 24
#define HSTAGE ((128 + 256) * PADH)   // halves per stage = 9216

__device__ __forceinline__ void mma16816(float* c, const uint32_t* a, const uint32_t* b) {
    asm volatile(
        "mma.sync.aligned.m16n8k16.row.col.f32.f16.f16.f32 "
        "{%0,%1,%2,%3}, {%4,%5,%6,%7}, {%8,%9}, {%0,%1,%2,%3};\n"
        : "+f"(c[0]), "+f"(c[1]), "+f"(c[2]), "+f"(c[3])
        : "r"(a[0]), "r"(a[1]), "r"(a[2]), "r"(a[3]), "r"(b[0]), "r"(b[1]));
}

__global__ void __launch_bounds__(256, 1)
gemm_f16_kernel(const float* __restrict__ A, const float* __restrict__ W,
                const float* __restrict__ bias, float* __restrict__ C, int act)
{
    extern __shared__ __half smh[];

    const int tid  = threadIdx.x;
    const int lane = tid & 31;
    const int wid  = tid >> 5;
    const int wm   = wid & 1;
    const int wn   = wid >> 1;
    const int g    = lane >> 2;
    const int tq   = lane & 3;
    const int m0   = blockIdx.y * 128;
    const int n0   = blockIdx.x * 256;

    float acc[4][8][4];
#pragma unroll
    for (int i = 0; i < 4; i++)
#pragma unroll
        for (int j = 0; j < 8; j++)
#pragma unroll
            for (int c = 0; c < 4; c++) acc[i][j][c] = 0.f;

    int arow[2], aco[2], brow[4], bco[4];
#pragma unroll
    for (int j = 0; j < 2; j++) { int id = tid + 256 * j; arow[j] = id >> 2; aco[j] = (id & 3) * 4; }
#pragma unroll
    for (int j = 0; j < 4; j++) { int id = tid + 256 * j; brow[j] = id >> 2; bco[j] = (id & 3) * 4; }

    const float* Ag = A + (size_t)m0 * DD;
    const float* Wg = W + (size_t)n0 * DD;

    float4 la[2], lb[4];

#pragma unroll
    for (int j = 0; j < 2; j++) la[j] = *(const float4*)(Ag + (size_t)arow[j] * DD + aco[j]);
#pragma unroll
    for (int j = 0; j < 4; j++) lb[j] = *(const float4*)(Wg + (size_t)brow[j] * DD + bco[j]);
    {
        __half* sA = smh;
        __half* sB = smh + 128 * PADH;
#pragma unroll
        for (int j = 0; j < 2; j++) {
            __half* p = sA + arow[j] * PADH + aco[j];
            *(__half2*)(p)     = __floats2half2_rn(la[j].x, la[j].y);
            *(__half2*)(p + 2) = __floats2half2_rn(la[j].z, la[j].w);
        }
#pragma unroll
        for (int j = 0; j < 4; j++) {
            __half* p = sB + brow[j] * PADH + bco[j];
            *(__half2*)(p)     = __floats2half2_rn(lb[j].x, lb[j].y);
            *(__half2*)(p + 2) = __floats2half2_rn(lb[j].z, lb[j].w);
        }
    }
    __syncthreads();

    for (int kt = 0; kt < 32; kt++) {
        if (kt < 31) {
            const int kk = (kt + 1) * 16;
#pragma unroll
            for (int j = 0; j < 2; j++)
                la[j] = *(const float4*)(Ag + (size_t)arow[j] * DD + kk + aco[j]);
#pragma unroll
            for (int j = 0; j < 4; j++)
                lb[j] = *(const float4*)(Wg + (size_t)brow[j] * DD + kk + bco[j]);
        }

        const __half* sA = smh + (kt & 1) * HSTAGE;
        const __half* sB = sA + 128 * PADH;

        uint32_t af[4][4], bf[8][2];
#pragma unroll
        for (int mi = 0; mi < 4; mi++) {
            const int r = wm * 64 + mi * 16 + g;
            af[mi][0] = *(const uint32_t*)(sA + r * PADH + 2 * tq);
            af[mi][1] = *(const uint32_t*)(sA + (r + 8) * PADH + 2 * tq);
            af[mi][2] = *(const uint32_t*)(sA + r * PADH + 2 * tq + 8);
            af[mi][3] = *(const uint32_t*)(sA + (r + 8) * PADH + 2 * tq + 8);
        }
#pragma unroll
        for (int ni = 0; ni < 8; ni++) {
            const int r = wn * 64 + ni * 8 + g;
            bf[ni][0] = *(const uint32_t*)(sB + r * PADH + 2 * tq);
            bf[ni][1] = *(const uint32_t*)(sB + r * PADH + 2 * tq + 8);
        }
#pragma unroll
        for (int mi = 0; mi < 4; mi++)
#pragma unroll
            for (int ni = 0; ni < 8; ni++)
                mma16816(acc[mi][ni], af[mi], bf[ni]);

        if (kt < 31) {
            __half* dA = smh + ((kt + 1) & 1) * HSTAGE;
            __half* dB = dA + 128 * PADH;
#pragma unroll
            for (int j = 0; j < 2; j++) {
                __half* p = dA + arow[j] * PADH + aco[j];
                *(__half2*)(p)     = __floats2half2_rn(la[j].x, la[j].y);
                *(__half2*)(p + 2) = __floats2half2_rn(la[j].z, la[j].w);
            }
#pragma unroll
            for (int j = 0; j < 4; j++) {
                __half* p = dB + brow[j] * PADH + bco[j];
                *(__half2*)(p)     = __floats2half2_rn(lb[j].x, lb[j].y);
                *(__half2*)(p + 2) = __floats2half2_rn(lb[j].z, lb[j].w);
            }
        }
        __syncthreads();
    }

#pragma unroll
    for (int mi = 0; mi < 4; mi++) {
        const int row = m0 + wm * 64 + mi * 16 + g;
#pragma unroll
        for (int ni = 0; ni < 8; ni++) {
            const int col = n0 + wn * 64 + ni * 8 + tq * 2;
            const float b0 = bias[col], b1 = bias[col + 1];
            float v0 = acc[mi][ni][0] + b0;
            float v1 = acc[mi][ni][1] + b1;
            float v2 = acc[mi][ni][2] + b0;
            float v3 = acc[mi][ni][3] + b1;
            if (act) {
                v0 = (v0 > 0.f) ? (v0 + 1.f) : __expf(v0);
                v1 = (v1 > 0.f) ? (v1 + 1.f) : __expf(v1);
                v2 = (v2 > 0.f) ? (v2 + 1.f) : __expf(v2);
                v3 = (v3 > 0.f) ? (v3 + 1.f) : __expf(v3);
            }
            *(float2*)(C + (size_t)row * DD + col)       = make_float2(v0, v1);
            *(float2*)(C + (size_t)(row + 8) * DD + col) = make_float2(v2, v3);
        }
    }
}

// ===========================================================================
// KV reduce (fp32, double-buffered): partial kv[d][m] = sum_s K[s][d]*V[s][m]
// ===========================================================================
__global__ void __launch_bounds__(256)
kv_reduce_kernel(const float* __restrict__ Kmat, const float* __restrict__ Vmat)
{
    const int bh = blockIdx.x;
    const int chunk = blockIdx.y;
    const int b = bh / HH, h = bh % HH;
    const int s_begin = chunk * (SS / KVC);  // 256 rows

    const float* Kbase = Kmat + (size_t)b * SS * DD + h * DHD;
    const float* Vbase = Vmat + (size_t)b * SS * DD + h * DHD;

    __shared__ float Ks[2][16][DHD];
    __shared__ float Vs[2][16][DHD];

    const int tid = threadIdx.x;
    const int tx = tid & 15;
    const int ty = tid >> 4;
    const int lr = tid >> 4;
    const int lc = (tid & 15) * 4;

    float acc[4][4];
#pragma unroll
    for (int i = 0; i < 4; i++)
#pragma unroll
        for (int j = 0; j < 4; j++) acc[i][j] = 0.f;
    float zacc = 0.f;

    float4 kk = *(const float4*)(Kbase + (size_t)(s_begin + lr) * DD + lc);
    float4 vv = *(const float4*)(Vbase + (size_t)(s_begin + lr) * DD + lc);
    *(float4*)&Ks[0][lr][lc] = kk;
    *(float4*)&Vs[0][lr][lc] = vv;
    __syncthreads();

    for (int t = 0; t < 16; t++) {
        if (t < 15) {
            const int srow = s_begin + (t + 1) * 16 + lr;
            kk = *(const float4*)(Kbase + (size_t)srow * DD + lc);
            vv = *(const float4*)(Vbase + (size_t)srow * DD + lc);
        }
        const int cur = t & 1;
#pragma unroll
        for (int ss = 0; ss < 16; ss++) {
            float4 a4 = *(const float4*)&Ks[cur][ss][ty * 4];
            float4 b4 = *(const float4*)&Vs[cur][ss][tx * 4];
            float a[4] = {a4.x, a4.y, a4.z, a4.w};
            float bb[4] = {b4.x, b4.y, b4.z, b4.w};
#pragma unroll
            for (int i = 0; i < 4; i++)
#pragma unroll
                for (int j = 0; j < 4; j++)
                    acc[i][j] = fmaf(a[i], bb[j], acc[i][j]);
        }
        if (tid < DHD) {
#pragma unroll
            for (int ss = 0; ss < 16; ss++) zacc += Ks[cur][ss][tid];
        }
        if (t < 15) {
            const int nxt = (t + 1) & 1;
            *(float4*)&Ks[nxt][lr][lc] = kk;
            *(float4*)&Vs[nxt][lr][lc] = vv;
        }
        __syncthreads();
    }

    float* kvp = g_kv_part + ((size_t)chunk * (BB * HH) + bh) * DHD * DHD;
#pragma unroll
    for (int i = 0; i < 4; i++) {
        const int d = ty * 4 + i;
        *(float4*)&kvp[d * DHD + tx * 4] = make_float4(acc[i][0], acc[i][1], acc[i][2], acc[i][3]);
    }
    if (tid < DHD)
        g_z_part[((size_t)chunk * (BB * HH) + bh) * DHD + tid] = zacc;
}

// ===========================================================================
// Finalize: sum partials -> dout (kv [d][m], z) + transposed fp16 g_kvT [m][d]
// ===========================================================================
__global__ void __launch_bounds__(256)
kv_finalize_kernel(float* __restrict__ dout, int write_out)
{
    const int idx = blockIdx.x * blockDim.x + threadIdx.x;
    if (idx < NKV) {
        float s = 0.f;
#pragma unroll
        for (int c = 0; c < KVC; c++) s += g_kv_part[(size_t)c * NKV + idx];
        const int bh = idx >> 12;
        const int rem = idx & 4095;
        const int d = rem >> 6;
        const int m = rem & 63;
        g_kvT[bh * 4096 + m * 64 + d] = __float2half(s);
        if (write_out) dout[OFF_KV + idx] = s;
    } else if (idx < NKV + NZ) {
        const int id2 = idx - NKV;
        float s = 0.f;
#pragma unroll
        for (int c = 0; c < KVC; c++) s += g_z_part[(size_t)c * NZ + id2];
        g_z[id2] = s;
        if (write_out) dout[OFF_Z + id2] = s;
    }
}

// ===========================================================================
// Fused attention + output GEMM:
//   out[m, n] = sum_h ( (Q_h[m,:] @ kv_h) / (Q_h[m,:]·z_h + eps) ) @ Wo_h^T + bo
// Per block: 128 rows x 256 out cols; loop over 8 head phases.
// ===========================================================================
#define FP 72   // padded halves per 64-col row

// smem byte offsets
#define QH_OFF   0
#define ATT_OFF  18432
#define KV_OFF   36864
#define WH_OFF   46080
#define DEN_OFF  82944
#define ZF_OFF   83456
#define FUSED_SMEM 83712

__global__ void __launch_bounds__(256, 1)
gemm_out_fused_kernel(const float* __restrict__ Q, const float* __restrict__ Wo,
                      const float* __restrict__ bo, float* __restrict__ out)
{
    extern __shared__ char smb[];
    __half* Qh   = (__half*)(smb + QH_OFF);
    __half* ATTh = (__half*)(smb + ATT_OFF);
    __half* KVh  = (__half*)(smb + KV_OFF);
    __half* Wh   = (__half*)(smb + WH_OFF);
    float* invden = (float*)(smb + DEN_OFF);
    float* zf     = (float*)(smb + ZF_OFF);

    const int tid  = threadIdx.x;
    const int lane = tid & 31;
    const int wid  = tid >> 5;
    const int wm   = wid & 1;
    const int wn   = wid >> 1;
    const int g    = lane >> 2;
    const int tq   = lane & 3;
    const int m0   = blockIdx.y * 128;
    const int n0   = blockIdx.x * 256;
    const int bidx = m0 >> 13;   // batch

    float acc[4][8][4];
#pragma unroll
    for (int i = 0; i < 4; i++)
#pragma unroll
        for (int j = 0; j < 8; j++)
#pragma unroll
            for (int c = 0; c < 4; c++) acc[i][j][c] = 0.f;

    for (int h = 0; h < HH; h++) {
        const int bh = bidx * HH + h;
        __syncthreads();   // protect smem from previous phase readers

        // --- load Q tile [128][64] fp32 -> fp16 ---
#pragma unroll
        for (int j = 0; j < 8; j++) {
            const int id = tid + 256 * j;
            const int row = id >> 4;
            const int c4 = (id & 15) * 4;
            float4 qv = *(const float4*)(Q + (size_t)(m0 + row) * DD + h * 64 + c4);
            __half* p = Qh + row * FP + c4;
            *(__half2*)(p)     = __floats2half2_rn(qv.x, qv.y);
            *(__half2*)(p + 2) = __floats2half2_rn(qv.z, qv.w);
        }
        // --- load kv_h^T [m][d] fp16 (direct word copy) ---
        {
            const uint32_t* src = (const uint32_t*)(g_kvT + (size_t)bh * 4096);
            uint32_t* dst = (uint32_t*)KVh;
#pragma unroll
            for (int j = 0; j < 8; j++) {
                const int w = tid + 256 * j;
                const int m = w >> 5;
                const int dw = w & 31;
                dst[m * (FP / 2) + dw] = src[w];
            }
        }
        if (tid < DHD) zf[tid] = g_z[bh * DHD + tid];
        // --- load Wo tile [256][64] fp32 -> fp16 ---
#pragma unroll
        for (int j = 0; j < 16; j++) {
            const int id = tid + 256 * j;
            const int row = id >> 4;
            const int c4 = (id & 15) * 4;
            float4 wv = *(const float4*)(Wo + (size_t)(n0 + row) * DD + h * 64 + c4);
            __half* p = Wh + row * FP + c4;
            *(__half2*)(p)     = __floats2half2_rn(wv.x, wv.y);
            *(__half2*)(p + 2) = __floats2half2_rn(wv.z, wv.w);
        }
        __syncthreads();

        // --- den: each pair of threads handles one row ---
        {
            const int r = tid >> 1;
            const int o = tid & 1;
            float s = 0.f;
            const __half2* qrow = (const __half2*)(Qh + r * FP) + o * 16;
#pragma unroll
            for (int i = 0; i < 16; i++) {
                float2 qf = __half22float2(qrow[i]);
                const int d = (o * 16 + i) * 2;
                s = fmaf(qf.x, zf[d], s);
                s = fmaf(qf.y, zf[d + 1], s);
            }
            s += __shfl_xor_sync(0xffffffffu, s, 1);
            if (o == 0) invden[r] = 1.0f / (s + EPSF);
        }
        __syncthreads();

        // --- att = Q @ kv (fp16 mma), scaled by invden, -> ATTh ---
        {
            float aacc[4][2][4];
#pragma unroll
            for (int i = 0; i < 4; i++)
#pragma unroll
                for (int j = 0; j < 2; j++)
#pragma unroll
                    for (int c = 0; c < 4; c++) aacc[i][j][c] = 0.f;

#pragma unroll
            for (int kt = 0; kt < 4; kt++) {
                uint32_t af[4][4], bf[2][2];
#pragma unroll
                for (int mi = 0; mi < 4; mi++) {
                    const int r = wm * 64 + mi * 16 + g;
                    const __half* p = Qh + r * FP + kt * 16 + 2 * tq;
                    af[mi][0] = *(const uint32_t*)(p);
                    af[mi][1] = *(const uint32_t*)(p + 8 * FP);
                    af[mi][2] = *(const uint32_t*)(p + 8);
                    af[mi][3] = *(const uint32_t*)(p + 8 * FP + 8);
                }
#pragma unroll
                for (int ni = 0; ni < 2; ni++) {
                    const int n = wn * 16 + ni * 8 + g;
                    const __half* p = KVh + n * FP + kt * 16 + 2 * tq;
                    bf[ni][0] = *(const uint32_t*)(p);
                    bf[ni][1] = *(const uint32_t*)(p + 8);
                }
#pragma unroll
                for (int mi = 0; mi < 4; mi++)
#pragma unroll
                    for (int ni = 0; ni < 2; ni++)
                        mma16816(aacc[mi][ni], af[mi], bf[ni]);
            }
            // scale + store fp16
#pragma unroll
            for (int mi = 0; mi < 4; mi++) {
                const int r = wm * 64 + mi * 16 + g;
                const float i0 = invden[r];
                const float i1 = invden[r + 8];
#pragma unroll
                for (int ni = 0; ni < 2; ni++) {
                    const int c = wn * 16 + ni * 8 + 2 * tq;
                    *(__half2*)(ATTh + r * FP + c) =
                        __floats2half2_rn(aacc[mi][ni][0] * i0, aacc[mi][ni][1] * i0);
                    *(__half2*)(ATTh + (r + 8) * FP + c) =
                        __floats2half2_rn(aacc[mi][ni][2] * i1, aacc[mi][ni][3] * i1);
                }
            }
        }
        __syncthreads();

        // --- main mma: acc += att @ Wo_h^T ---
#pragma unroll
        for (int kt = 0; kt < 4; kt++) {
            uint32_t af[4][4], bf[8][2];
#pragma unroll
            for (int mi = 0; mi < 4; mi++) {
                const int r = wm * 64 + mi * 16 + g;
                const __half* p = ATTh + r * FP + kt * 16 + 2 * tq;
                af[mi][0] = *(const uint32_t*)(p);
                af[mi][1] = *(const uint32_t*)(p + 8 * FP);
                af[mi][2] = *(const uint32_t*)(p + 8);
                af[mi][3] = *(const uint32_t*)(p + 8 * FP + 8);
            }
#pragma unroll
            for (int ni = 0; ni < 8; ni++) {
                const int n = wn * 64 + ni * 8 + g;
                const __half* p = Wh + n * FP + kt * 16 + 2 * tq;
                bf[ni][0] = *(const uint32_t*)(p);
                bf[ni][1] = *(const uint32_t*)(p + 8);
            }
#pragma unroll
            for (int mi = 0; mi < 4; mi++)
#pragma unroll
                for (int ni = 0; ni < 8; ni++)
                    mma16816(acc[mi][ni], af[mi], bf[ni]);
        }
    }

    // epilogue: + bo
#pragma unroll
    for (int mi = 0; mi < 4; mi++) {
        const int row = m0 + wm * 64 + mi * 16 + g;
#pragma unroll
        for (int ni = 0; ni < 8; ni++) {
            const int col = n0 + wn * 64 + ni * 8 + tq * 2;
            const float b0 = bo[col], b1 = bo[col + 1];
            *(float2*)(out + (size_t)row * DD + col) =
                make_float2(acc[mi][ni][0] + b0, acc[mi][ni][1] + b1);
            *(float2*)(out + (size_t)(row + 8) * DD + col) =
                make_float2(acc[mi][ni][2] + b0, acc[mi][ni][3] + b1);
        }
    }
}

// ===========================================================================
// Launch
// ===========================================================================
extern "C" void kernel_launch(void* const* d_in, const int* in_sizes, int n_in,
                              void* d_out, int out_size)
{
    const float* q  = (const float*)d_in[0];
    const float* k  = (const float*)d_in[1];
    const float* v  = (const float*)d_in[2];
    const float* Wq = (const float*)d_in[3];
    const float* bq = (const float*)d_in[4];
    const float* Wk = (const float*)d_in[5];
    const float* bk = (const float*)d_in[6];
    const float* Wv = (const float*)d_in[7];
    const float* bv = (const float*)d_in[8];
    const float* Wo = (const float*)d_in[9];
    const float* bo = (const float*)d_in[10];
    float* out = (float*)d_out;

    float *gQ, *gK, *gV;
    cudaGetSymbolAddress((void**)&gQ, g_Q);
    cudaGetSymbolAddress((void**)&gK, g_K);
    cudaGetSymbolAddress((void**)&gV, g_V);

    const int write_extra = ((size_t)out_size >= OFF_Z + NZ) ? 1 : 0;

    const int gemm_smem = 2 * HSTAGE * 2;   // 36864 bytes
    cudaFuncSetAttribute(gemm_f16_kernel,
                         cudaFuncAttributeMaxDynamicSharedMemorySize, gemm_smem);
    cudaFuncSetAttribute(gemm_out_fused_kernel,
                         cudaFuncAttributeMaxDynamicSharedMemorySize, FUSED_SMEM);

    dim3 gemm_grid(DD / 256, MR / 128);     // (2, 256)
    gemm_f16_kernel<<<gemm_grid, 256, gemm_smem>>>(q, Wq, bq, gQ, 1);
    gemm_f16_kernel<<<gemm_grid, 256, gemm_smem>>>(k, Wk, bk, gK, 1);
    gemm_f16_kernel<<<gemm_grid, 256, gemm_smem>>>(v, Wv, bv, gV, 0);

    dim3 kv_grid(BB * HH, KVC);             // (32, 32)
    kv_reduce_kernel<<<kv_grid, 256>>>(gK, gV);

    const int fin_total = NKV + NZ;
    kv_finalize_kernel<<<(fin_total + 255) / 256, 256>>>(out, write_extra);

    gemm_out_fused_kernel<<<gemm_grid, 256, FUSED_SMEM>>>(gQ, Wo, bo, out);
}

// round 9
// speedup vs baseline: 3.6224x; 1.0790x over previous
#include <cuda_runtime.h>
#include <cuda_fp16.h>
#include <cstdint>

// Problem constants
#define BB 4
#define SS 8192
#define DD 512
#define HH 8
#define DHD 64
#define MR (BB*SS)          // 32768 rows
#define EPSF 1e-6f
#define KVC 32              // s-chunks for kv reduction

// Output layout (concatenated tuple): out [B,S,D], k_v [B,H,DH,DH], z [B,H,DH]
#define OFF_KV ((size_t)MR*DD)                     // 16777216
#define NKV (BB*HH*DHD*DHD)                        // 131072
#define OFF_Z (OFF_KV + NKV)                       // 16908288
#define NZ (BB*HH*DHD)                             // 2048

// Scratch (device globals; no allocations allowed)
__device__ float g_Q[(size_t)MR*DD];
__device__ float g_K[(size_t)MR*DD];
__device__ float g_V[(size_t)MR*DD];
__device__ float g_kv_part[(size_t)KVC*BB*HH*DHD*DHD];
__device__ float g_z_part[(size_t)KVC*BB*HH*DHD];
__device__ __half g_kvT[NKV];   // transposed [b,h,m,d] fp16 for fused out-GEMM
__device__ float g_z[NZ];

__device__ __forceinline__ void mma16816(float* c, const uint32_t* a, const uint32_t* b) {
    asm volatile(
        "mma.sync.aligned.m16n8k16.row.col.f32.f16.f16.f32 "
        "{%0,%1,%2,%3}, {%4,%5,%6,%7}, {%8,%9}, {%0,%1,%2,%3};\n"
        : "+f"(c[0]), "+f"(c[1]), "+f"(c[2]), "+f"(c[3])
        : "r"(a[0]), "r"(a[1]), "r"(a[2]), "r"(a[3]), "r"(b[0]), "r"(b[1]));
}

__device__ __forceinline__ void ldsm4(uint32_t* r, uint32_t addr) {
    asm volatile("ldmatrix.sync.aligned.m8n8.x4.shared.b16 {%0,%1,%2,%3}, [%4];"
        : "=r"(r[0]), "=r"(r[1]), "=r"(r[2]), "=r"(r[3]) : "r"(addr));
}

// ===========================================================================
// fp16 tensor-core GEMM: C[M,512] = A[M,512] @ W[512,512]^T + bias, opt elu+1
// BM=128, BN=256, BK=32, 512 threads (16 warps 4x4), warp tile 32x64.
// ldmatrix fragment loads, double-buffered smem, 1 sync per K-iter (16 iters).
// ===========================================================================
#define PADH 40
#define STG_H ((128 + 256) * PADH)   // halves per stage = 15360

__global__ void __launch_bounds__(512, 1)
gemm_f16_kernel(const float* __restrict__ A, const float* __restrict__ W,
                const float* __restrict__ bias, float* __restrict__ C, int act)
{
    extern __shared__ __half smh[];
    const uint32_t sbase = (uint32_t)__cvta_generic_to_shared(smh);

    const int tid  = threadIdx.x;
    const int lane = tid & 31;
    const int wid  = tid >> 5;
    const int wm   = wid & 3;        // 4 m-warps * 32 rows
    const int wn   = wid >> 2;       // 4 n-warps * 64 cols
    const int g    = lane >> 2;
    const int tq   = lane & 3;
    const int m0   = blockIdx.y * 128;
    const int n0   = blockIdx.x * 256;

    float acc[2][8][4];
#pragma unroll
    for (int i = 0; i < 2; i++)
#pragma unroll
        for (int j = 0; j < 8; j++)
#pragma unroll
            for (int c = 0; c < 4; c++) acc[i][j][c] = 0.f;

    // Global-load map (BK=32): A 1024 float4, B 2048 float4, 512 threads
    int arow[2], aco[2], brow[4], bco[4];
#pragma unroll
    for (int j = 0; j < 2; j++) { int id = tid + 512 * j; arow[j] = id >> 3; aco[j] = (id & 7) * 4; }
#pragma unroll
    for (int j = 0; j < 4; j++) { int id = tid + 512 * j; brow[j] = id >> 3; bco[j] = (id & 7) * 4; }

    // ldmatrix per-thread half-offsets (k-offset added in loop)
    uint32_t aoff[2], boff[4];
#pragma unroll
    for (int mi = 0; mi < 2; mi++)
        aoff[mi] = (wm * 32 + mi * 16 + (lane & 15)) * PADH + ((lane >> 4) << 3);
#pragma unroll
    for (int pi = 0; pi < 4; pi++)
        boff[pi] = (128 + wn * 64 + pi * 16 + (lane & 7) + ((lane & 16) >> 1)) * PADH + (lane & 8);

    const float* Ag = A + (size_t)m0 * DD;
    const float* Wg = W + (size_t)n0 * DD;

    float4 la[2], lb[4];

#pragma unroll
    for (int j = 0; j < 2; j++) la[j] = *(const float4*)(Ag + (size_t)arow[j] * DD + aco[j]);
#pragma unroll
    for (int j = 0; j < 4; j++) lb[j] = *(const float4*)(Wg + (size_t)brow[j] * DD + bco[j]);
    {
        __half* sA = smh;
        __half* sB = smh + 128 * PADH;
#pragma unroll
        for (int j = 0; j < 2; j++) {
            __half* p = sA + arow[j] * PADH + aco[j];
            *(__half2*)(p)     = __floats2half2_rn(la[j].x, la[j].y);
            *(__half2*)(p + 2) = __floats2half2_rn(la[j].z, la[j].w);
        }
#pragma unroll
        for (int j = 0; j < 4; j++) {
            __half* p = sB + brow[j] * PADH + bco[j];
            *(__half2*)(p)     = __floats2half2_rn(lb[j].x, lb[j].y);
            *(__half2*)(p + 2) = __floats2half2_rn(lb[j].z, lb[j].w);
        }
    }
    __syncthreads();

    for (int kt = 0; kt < 16; kt++) {
        if (kt < 15) {
            const int kk = (kt + 1) * 32;
#pragma unroll
            for (int j = 0; j < 2; j++)
                la[j] = *(const float4*)(Ag + (size_t)arow[j] * DD + kk + aco[j]);
#pragma unroll
            for (int j = 0; j < 4; j++)
                lb[j] = *(const float4*)(Wg + (size_t)brow[j] * DD + kk + bco[j]);
        }

        const uint32_t stg = sbase + (uint32_t)((kt & 1) * STG_H * 2);

#pragma unroll
        for (int ks = 0; ks < 32; ks += 16) {
            uint32_t af[2][4], bf[8][2];
#pragma unroll
            for (int mi = 0; mi < 2; mi++)
                ldsm4(af[mi], stg + (aoff[mi] + ks) * 2);
#pragma unroll
            for (int pi = 0; pi < 4; pi++) {
                uint32_t r[4];
                ldsm4(r, stg + (boff[pi] + ks) * 2);
                bf[2 * pi][0] = r[0]; bf[2 * pi][1] = r[1];
                bf[2 * pi + 1][0] = r[2]; bf[2 * pi + 1][1] = r[3];
            }
#pragma unroll
            for (int mi = 0; mi < 2; mi++)
#pragma unroll
                for (int ni = 0; ni < 8; ni++)
                    mma16816(acc[mi][ni], af[mi], bf[ni]);
        }

        if (kt < 15) {
            __half* dA = smh + ((kt + 1) & 1) * STG_H;
            __half* dB = dA + 128 * PADH;
#pragma unroll
            for (int j = 0; j < 2; j++) {
                __half* p = dA + arow[j] * PADH + aco[j];
                *(__half2*)(p)     = __floats2half2_rn(la[j].x, la[j].y);
                *(__half2*)(p + 2) = __floats2half2_rn(la[j].z, la[j].w);
            }
#pragma unroll
            for (int j = 0; j < 4; j++) {
                __half* p = dB + brow[j] * PADH + bco[j];
                *(__half2*)(p)     = __floats2half2_rn(lb[j].x, lb[j].y);
                *(__half2*)(p + 2) = __floats2half2_rn(lb[j].z, lb[j].w);
            }
        }
        __syncthreads();
    }

#pragma unroll
    for (int mi = 0; mi < 2; mi++) {
        const int row = m0 + wm * 32 + mi * 16 + g;
#pragma unroll
        for (int ni = 0; ni < 8; ni++) {
            const int col = n0 + wn * 64 + ni * 8 + tq * 2;
            const float b0 = bias[col], b1 = bias[col + 1];
            float v0 = acc[mi][ni][0] + b0;
            float v1 = acc[mi][ni][1] + b1;
            float v2 = acc[mi][ni][2] + b0;
            float v3 = acc[mi][ni][3] + b1;
            if (act) {
                v0 = (v0 > 0.f) ? (v0 + 1.f) : __expf(v0);
                v1 = (v1 > 0.f) ? (v1 + 1.f) : __expf(v1);
                v2 = (v2 > 0.f) ? (v2 + 1.f) : __expf(v2);
                v3 = (v3 > 0.f) ? (v3 + 1.f) : __expf(v3);
            }
            *(float2*)(C + (size_t)row * DD + col)       = make_float2(v0, v1);
            *(float2*)(C + (size_t)(row + 8) * DD + col) = make_float2(v2, v3);
        }
    }
}

// ===========================================================================
// KV reduce (fp32, double-buffered): partial kv[d][m] = sum_s K[s][d]*V[s][m]
// ===========================================================================
__global__ void __launch_bounds__(256)
kv_reduce_kernel(const float* __restrict__ Kmat, const float* __restrict__ Vmat)
{
    const int bh = blockIdx.x;
    const int chunk = blockIdx.y;
    const int b = bh / HH, h = bh % HH;
    const int s_begin = chunk * (SS / KVC);  // 256 rows

    const float* Kbase = Kmat + (size_t)b * SS * DD + h * DHD;
    const float* Vbase = Vmat + (size_t)b * SS * DD + h * DHD;

    __shared__ float Ks[2][16][DHD];
    __shared__ float Vs[2][16][DHD];

    const int tid = threadIdx.x;
    const int tx = tid & 15;
    const int ty = tid >> 4;
    const int lr = tid >> 4;
    const int lc = (tid & 15) * 4;

    float acc[4][4];
#pragma unroll
    for (int i = 0; i < 4; i++)
#pragma unroll
        for (int j = 0; j < 4; j++) acc[i][j] = 0.f;
    float zacc = 0.f;

    float4 kk = *(const float4*)(Kbase + (size_t)(s_begin + lr) * DD + lc);
    float4 vv = *(const float4*)(Vbase + (size_t)(s_begin + lr) * DD + lc);
    *(float4*)&Ks[0][lr][lc] = kk;
    *(float4*)&Vs[0][lr][lc] = vv;
    __syncthreads();

    for (int t = 0; t < 16; t++) {
        if (t < 15) {
            const int srow = s_begin + (t + 1) * 16 + lr;
            kk = *(const float4*)(Kbase + (size_t)srow * DD + lc);
            vv = *(const float4*)(Vbase + (size_t)srow * DD + lc);
        }
        const int cur = t & 1;
#pragma unroll
        for (int ss = 0; ss < 16; ss++) {
            float4 a4 = *(const float4*)&Ks[cur][ss][ty * 4];
            float4 b4 = *(const float4*)&Vs[cur][ss][tx * 4];
            float a[4] = {a4.x, a4.y, a4.z, a4.w};
            float bb[4] = {b4.x, b4.y, b4.z, b4.w};
#pragma unroll
            for (int i = 0; i < 4; i++)
#pragma unroll
                for (int j = 0; j < 4; j++)
                    acc[i][j] = fmaf(a[i], bb[j], acc[i][j]);
        }
        if (tid < DHD) {
#pragma unroll
            for (int ss = 0; ss < 16; ss++) zacc += Ks[cur][ss][tid];
        }
        if (t < 15) {
            const int nxt = (t + 1) & 1;
            *(float4*)&Ks[nxt][lr][lc] = kk;
            *(float4*)&Vs[nxt][lr][lc] = vv;
        }
        __syncthreads();
    }

    float* kvp = g_kv_part + ((size_t)chunk * (BB * HH) + bh) * DHD * DHD;
#pragma unroll
    for (int i = 0; i < 4; i++) {
        const int d = ty * 4 + i;
        *(float4*)&kvp[d * DHD + tx * 4] = make_float4(acc[i][0], acc[i][1], acc[i][2], acc[i][3]);
    }
    if (tid < DHD)
        g_z_part[((size_t)chunk * (BB * HH) + bh) * DHD + tid] = zacc;
}

// ===========================================================================
// Finalize: sum partials -> dout (kv [d][m], z) + transposed fp16 g_kvT [m][d]
// ===========================================================================
__global__ void __launch_bounds__(256)
kv_finalize_kernel(float* __restrict__ dout, int write_out)
{
    const int idx = blockIdx.x * blockDim.x + threadIdx.x;
    if (idx < NKV) {
        float s = 0.f;
#pragma unroll
        for (int c = 0; c < KVC; c++) s += g_kv_part[(size_t)c * NKV + idx];
        const int bh = idx >> 12;
        const int rem = idx & 4095;
        const int d = rem >> 6;
        const int m = rem & 63;
        g_kvT[bh * 4096 + m * 64 + d] = __float2half(s);
        if (write_out) dout[OFF_KV + idx] = s;
    } else if (idx < NKV + NZ) {
        const int id2 = idx - NKV;
        float s = 0.f;
#pragma unroll
        for (int c = 0; c < KVC; c++) s += g_z_part[(size_t)c * NZ + id2];
        g_z[id2] = s;
        if (write_out) dout[OFF_Z + id2] = s;
    }
}

// ===========================================================================
// Fused attention + output GEMM (512 threads, ldmatrix):
//   out[m,n] = sum_h ((Q_h[m,:] @ kv_h) / (Q_h[m,:].z_h + eps)) @ Wo_h^T + bo
// ===========================================================================
#define FP 72   // padded halves per 64-col row (stride 144B, ldmatrix conflict-free)

#define QH_OFF   0
#define ATT_OFF  18432
#define KV_OFF   36864
#define WH_OFF   46080
#define DEN_OFF  82944
#define ZF_OFF   83456
#define FUSED_SMEM 83712

__global__ void __launch_bounds__(512, 1)
gemm_out_fused_kernel(const float* __restrict__ Q, const float* __restrict__ Wo,
                      const float* __restrict__ bo, float* __restrict__ out)
{
    extern __shared__ char smb[];
    __half* Qh   = (__half*)(smb + QH_OFF);
    __half* ATTh = (__half*)(smb + ATT_OFF);
    __half* KVh  = (__half*)(smb + KV_OFF);
    __half* Wh   = (__half*)(smb + WH_OFF);
    float* invden = (float*)(smb + DEN_OFF);
    float* zf     = (float*)(smb + ZF_OFF);
    const uint32_t sbase = (uint32_t)__cvta_generic_to_shared(smb);

    const int tid  = threadIdx.x;
    const int lane = tid & 31;
    const int wid  = tid >> 5;
    const int wm   = wid & 3;        // rows wm*32
    const int wn   = wid >> 2;       // main cols wn*64 ; att cols wn*16
    const int g    = lane >> 2;
    const int tq   = lane & 3;
    const int m0   = blockIdx.y * 128;
    const int n0   = blockIdx.x * 256;
    const int bidx = m0 >> 13;       // batch

    // ldmatrix half-offsets
    uint32_t qoff[2], attoff[2], kvoff, woff[4];
#pragma unroll
    for (int mi = 0; mi < 2; mi++) {
        const uint32_t r = wm * 32 + mi * 16 + (lane & 15);
        const uint32_t kh = (lane >> 4) << 3;
        qoff[mi]   = (uint32_t)(QH_OFF / 2)  + r * FP + kh;
        attoff[mi] = (uint32_t)(ATT_OFF / 2) + r * FP + kh;
    }
    kvoff = (uint32_t)(KV_OFF / 2) + (wn * 16 + (lane & 7) + ((lane & 16) >> 1)) * FP + (lane & 8);
#pragma unroll
    for (int pi = 0; pi < 4; pi++)
        woff[pi] = (uint32_t)(WH_OFF / 2) + (wn * 64 + pi * 16 + (lane & 7) + ((lane & 16) >> 1)) * FP + (lane & 8);

    float acc[2][8][4];
#pragma unroll
    for (int i = 0; i < 2; i++)
#pragma unroll
        for (int j = 0; j < 8; j++)
#pragma unroll
            for (int c = 0; c < 4; c++) acc[i][j][c] = 0.f;

    for (int h = 0; h < HH; h++) {
        const int bh = bidx * HH + h;
        __syncthreads();   // protect smem from previous phase readers

        // --- load Q tile [128][64] fp32 -> fp16 ---
#pragma unroll
        for (int j = 0; j < 4; j++) {
            const int id = tid + 512 * j;
            const int row = id >> 4;
            const int c4 = (id & 15) * 4;
            float4 qv = *(const float4*)(Q + (size_t)(m0 + row) * DD + h * 64 + c4);
            __half* p = Qh + row * FP + c4;
            *(__half2*)(p)     = __floats2half2_rn(qv.x, qv.y);
            *(__half2*)(p + 2) = __floats2half2_rn(qv.z, qv.w);
        }
        // --- load kv_h^T [m][d] fp16 ---
        {
            const uint32_t* src = (const uint32_t*)(g_kvT + (size_t)bh * 4096);
            uint32_t* dst = (uint32_t*)KVh;
#pragma unroll
            for (int j = 0; j < 4; j++) {
                const int w = tid + 512 * j;
                const int m = w >> 5;
                const int dw = w & 31;
                dst[m * (FP / 2) + dw] = src[w];
            }
        }
        if (tid < DHD) zf[tid] = g_z[bh * DHD + tid];
        // --- load Wo tile [256][64] fp32 -> fp16 ---
#pragma unroll
        for (int j = 0; j < 8; j++) {
            const int id = tid + 512 * j;
            const int row = id >> 4;
            const int c4 = (id & 15) * 4;
            float4 wv = *(const float4*)(Wo + (size_t)(n0 + row) * DD + h * 64 + c4);
            __half* p = Wh + row * FP + c4;
            *(__half2*)(p)     = __floats2half2_rn(wv.x, wv.y);
            *(__half2*)(p + 2) = __floats2half2_rn(wv.z, wv.w);
        }
        __syncthreads();

        // --- den: 4 threads per row ---
        {
            const int r = tid >> 2;
            const int o = tid & 3;
            float s = 0.f;
            const __half2* qrow = (const __half2*)(Qh + r * FP) + o * 8;
#pragma unroll
            for (int i = 0; i < 8; i++) {
                float2 qf = __half22float2(qrow[i]);
                const int d = o * 16 + i * 2;
                s = fmaf(qf.x, zf[d], s);
                s = fmaf(qf.y, zf[d + 1], s);
            }
            s += __shfl_xor_sync(0xffffffffu, s, 1);
            s += __shfl_xor_sync(0xffffffffu, s, 2);
            if (o == 0) invden[r] = 1.0f / (s + EPSF);
        }
        __syncthreads();

        // --- att = Q @ kv (fp16 mma), scaled by invden, -> ATTh ---
        {
            float aacc[2][2][4];
#pragma unroll
            for (int i = 0; i < 2; i++)
#pragma unroll
                for (int j = 0; j < 2; j++)
#pragma unroll
                    for (int c = 0; c < 4; c++) aacc[i][j][c] = 0.f;

#pragma unroll
            for (int kt = 0; kt < 4; kt++) {
                uint32_t af[2][4], bf[2][2];
#pragma unroll
                for (int mi = 0; mi < 2; mi++)
                    ldsm4(af[mi], sbase + (qoff[mi] + kt * 16) * 2);
                {
                    uint32_t r[4];
                    ldsm4(r, sbase + (kvoff + kt * 16) * 2);
                    bf[0][0] = r[0]; bf[0][1] = r[1];
                    bf[1][0] = r[2]; bf[1][1] = r[3];
                }
#pragma unroll
                for (int mi = 0; mi < 2; mi++)
#pragma unroll
                    for (int ni = 0; ni < 2; ni++)
                        mma16816(aacc[mi][ni], af[mi], bf[ni]);
            }
#pragma unroll
            for (int mi = 0; mi < 2; mi++) {
                const int r = wm * 32 + mi * 16 + g;
                const float i0 = invden[r];
                const float i1 = invden[r + 8];
#pragma unroll
                for (int ni = 0; ni < 2; ni++) {
                    const int c = wn * 16 + ni * 8 + 2 * tq;
                    *(__half2*)(ATTh + r * FP + c) =
                        __floats2half2_rn(aacc[mi][ni][0] * i0, aacc[mi][ni][1] * i0);
                    *(__half2*)(ATTh + (r + 8) * FP + c) =
                        __floats2half2_rn(aacc[mi][ni][2] * i1, aacc[mi][ni][3] * i1);
                }
            }
        }
        __syncthreads();

        // --- main mma: acc += att @ Wo_h^T ---
#pragma unroll
        for (int kt = 0; kt < 4; kt++) {
            uint32_t af[2][4], bf[8][2];
#pragma unroll
            for (int mi = 0; mi < 2; mi++)
                ldsm4(af[mi], sbase + (attoff[mi] + kt * 16) * 2);
#pragma unroll
            for (int pi = 0; pi < 4; pi++) {
                uint32_t r[4];
                ldsm4(r, sbase + (woff[pi] + kt * 16) * 2);
                bf[2 * pi][0] = r[0]; bf[2 * pi][1] = r[1];
                bf[2 * pi + 1][0] = r[2]; bf[2 * pi + 1][1] = r[3];
            }
#pragma unroll
            for (int mi = 0; mi < 2; mi++)
#pragma unroll
                for (int ni = 0; ni < 8; ni++)
                    mma16816(acc[mi][ni], af[mi], bf[ni]);
        }
    }

    // epilogue: + bo
#pragma unroll
    for (int mi = 0; mi < 2; mi++) {
        const int row = m0 + wm * 32 + mi * 16 + g;
#pragma unroll
        for (int ni = 0; ni < 8; ni++) {
            const int col = n0 + wn * 64 + ni * 8 + tq * 2;
            const float b0 = bo[col], b1 = bo[col + 1];
            *(float2*)(out + (size_t)row * DD + col) =
                make_float2(acc[mi][ni][0] + b0, acc[mi][ni][1] + b1);
            *(float2*)(out + (size_t)(row + 8) * DD + col) =
                make_float2(acc[mi][ni][2] + b0, acc[mi][ni][3] + b1);
        }
    }
}

// ===========================================================================
// Launch
// ===========================================================================
extern "C" void kernel_launch(void* const* d_in, const int* in_sizes, int n_in,
                              void* d_out, int out_size)
{
    const float* q  = (const float*)d_in[0];
    const float* k  = (const float*)d_in[1];
    const float* v  = (const float*)d_in[2];
    const float* Wq = (const float*)d_in[3];
    const float* bq = (const float*)d_in[4];
    const float* Wk = (const float*)d_in[5];
    const float* bk = (const float*)d_in[6];
    const float* Wv = (const float*)d_in[7];
    const float* bv = (const float*)d_in[8];
    const float* Wo = (const float*)d_in[9];
    const float* bo = (const float*)d_in[10];
    float* out = (float*)d_out;

    float *gQ, *gK, *gV;
    cudaGetSymbolAddress((void**)&gQ, g_Q);
    cudaGetSymbolAddress((void**)&gK, g_K);
    cudaGetSymbolAddress((void**)&gV, g_V);

    const int write_extra = ((size_t)out_size >= OFF_Z + NZ) ? 1 : 0;

    const int gemm_smem = 2 * STG_H * 2;   // 61440 bytes
    cudaFuncSetAttribute(gemm_f16_kernel,
                         cudaFuncAttributeMaxDynamicSharedMemorySize, gemm_smem);
    cudaFuncSetAttribute(gemm_out_fused_kernel,
                         cudaFuncAttributeMaxDynamicSharedMemorySize, FUSED_SMEM);

    dim3 gemm_grid(DD / 256, MR / 128);     // (2, 256)
    gemm_f16_kernel<<<gemm_grid, 512, gemm_smem>>>(k, Wk, bk, gK, 1);
    gemm_f16_kernel<<<gemm_grid, 512, gemm_smem>>>(v, Wv, bv, gV, 0);
    gemm_f16_kernel<<<gemm_grid, 512, gemm_smem>>>(q, Wq, bq, gQ, 1);

    dim3 kv_grid(BB * HH, KVC);             // (32, 32)
    kv_reduce_kernel<<<kv_grid, 256>>>(gK, gV);

    const int fin_total = NKV + NZ;
    kv_finalize_kernel<<<(fin_total + 255) / 256, 256>>>(out, write_extra);

    gemm_out_fused_kernel<<<gemm_grid, 512, FUSED_SMEM>>>(gQ, Wo, bo, out);
}

// round 11
// speedup vs baseline: 3.9800x; 1.0987x over previous
#include <cuda_runtime.h>
#include <cuda_fp16.h>
#include <cstdint>

// Problem constants
#define BB 4
#define SS 8192
#define DD 512
#define HH 8
#define DHD 64
#define MR (BB*SS)          // 32768 rows
#define EPSF 1e-6f
#define KVC 32              // s-chunks for kv reduction

// Output layout (concatenated tuple): out [B,S,D], k_v [B,H,DH,DH], z [B,H,DH]
#define OFF_KV ((size_t)MR*DD)                     // 16777216
#define NKV (BB*HH*DHD*DHD)                        // 131072
#define OFF_Z (OFF_KV + NKV)                       // 16908288
#define NZ (BB*HH*DHD)                             // 2048

// Scratch (device globals; no allocations allowed) — intermediates now fp16
__device__ __half g_Q[(size_t)MR*DD];
__device__ __half g_K[(size_t)MR*DD];
__device__ __half g_V[(size_t)MR*DD];
__device__ float g_kv_part[(size_t)KVC*BB*HH*DHD*DHD];  // [chunk][bh][m*64+d]
__device__ float g_z_part[(size_t)KVC*BB*HH*DHD];
__device__ __half g_kvT[NKV];   // [b,h,m,d] fp16 for fused out-GEMM
__device__ float g_z[NZ];

__device__ __forceinline__ void mma16816(float* c, const uint32_t* a, const uint32_t* b) {
    asm volatile(
        "mma.sync.aligned.m16n8k16.row.col.f32.f16.f16.f32 "
        "{%0,%1,%2,%3}, {%4,%5,%6,%7}, {%8,%9}, {%0,%1,%2,%3};\n"
        : "+f"(c[0]), "+f"(c[1]), "+f"(c[2]), "+f"(c[3])
        : "r"(a[0]), "r"(a[1]), "r"(a[2]), "r"(a[3]), "r"(b[0]), "r"(b[1]));
}

__device__ __forceinline__ void ldsm4(uint32_t* r, uint32_t addr) {
    asm volatile("ldmatrix.sync.aligned.m8n8.x4.shared.b16 {%0,%1,%2,%3}, [%4];"
        : "=r"(r[0]), "=r"(r[1]), "=r"(r[2]), "=r"(r[3]) : "r"(addr));
}

__device__ __forceinline__ void ldsm4t(uint32_t* r, uint32_t addr) {
    asm volatile("ldmatrix.sync.aligned.m8n8.x4.trans.shared.b16 {%0,%1,%2,%3}, [%4];"
        : "=r"(r[0]), "=r"(r[1]), "=r"(r[2]), "=r"(r[3]) : "r"(addr));
}

// ===========================================================================
// fp16 tensor-core GEMM: C[M,512] = A[M,512] @ W[512,512]^T + bias, opt elu+1
// fp32 in, fp16 out. BM=128, BN=256, BK=32, 512 threads, warp tile 32x64.
// ===========================================================================
#define PADH 40
#define STG_H ((128 + 256) * PADH)   // halves per stage = 15360

__global__ void __launch_bounds__(512, 1)
gemm_f16_kernel(const float* __restrict__ A, const float* __restrict__ W,
                const float* __restrict__ bias, __half* __restrict__ C, int act)
{
    extern __shared__ __half smh[];
    const uint32_t sbase = (uint32_t)__cvta_generic_to_shared(smh);

    const int tid  = threadIdx.x;
    const int lane = tid & 31;
    const int wid  = tid >> 5;
    const int wm   = wid & 3;
    const int wn   = wid >> 2;
    const int g    = lane >> 2;
    const int tq   = lane & 3;
    const int m0   = blockIdx.y * 128;
    const int n0   = blockIdx.x * 256;

    float acc[2][8][4];
#pragma unroll
    for (int i = 0; i < 2; i++)
#pragma unroll
        for (int j = 0; j < 8; j++)
#pragma unroll
            for (int c = 0; c < 4; c++) acc[i][j][c] = 0.f;

    int arow[2], aco[2], brow[4], bco[4];
#pragma unroll
    for (int j = 0; j < 2; j++) { int id = tid + 512 * j; arow[j] = id >> 3; aco[j] = (id & 7) * 4; }
#pragma unroll
    for (int j = 0; j < 4; j++) { int id = tid + 512 * j; brow[j] = id >> 3; bco[j] = (id & 7) * 4; }

    uint32_t aoff[2], boff[4];
#pragma unroll
    for (int mi = 0; mi < 2; mi++)
        aoff[mi] = (wm * 32 + mi * 16 + (lane & 15)) * PADH + ((lane >> 4) << 3);
#pragma unroll
    for (int pi = 0; pi < 4; pi++)
        boff[pi] = (128 + wn * 64 + pi * 16 + (lane & 7) + ((lane & 16) >> 1)) * PADH + (lane & 8);

    const float* Ag = A + (size_t)m0 * DD;
    const float* Wg = W + (size_t)n0 * DD;

    float4 la[2], lb[4];

#pragma unroll
    for (int j = 0; j < 2; j++) la[j] = *(const float4*)(Ag + (size_t)arow[j] * DD + aco[j]);
#pragma unroll
    for (int j = 0; j < 4; j++) lb[j] = *(const float4*)(Wg + (size_t)brow[j] * DD + bco[j]);
    {
        __half* sA = smh;
        __half* sB = smh + 128 * PADH;
#pragma unroll
        for (int j = 0; j < 2; j++) {
            __half* p = sA + arow[j] * PADH + aco[j];
            *(__half2*)(p)     = __floats2half2_rn(la[j].x, la[j].y);
            *(__half2*)(p + 2) = __floats2half2_rn(la[j].z, la[j].w);
        }
#pragma unroll
        for (int j = 0; j < 4; j++) {
            __half* p = sB + brow[j] * PADH + bco[j];
            *(__half2*)(p)     = __floats2half2_rn(lb[j].x, lb[j].y);
            *(__half2*)(p + 2) = __floats2half2_rn(lb[j].z, lb[j].w);
        }
    }
    __syncthreads();

    for (int kt = 0; kt < 16; kt++) {
        if (kt < 15) {
            const int kk = (kt + 1) * 32;
#pragma unroll
            for (int j = 0; j < 2; j++)
                la[j] = *(const float4*)(Ag + (size_t)arow[j] * DD + kk + aco[j]);
#pragma unroll
            for (int j = 0; j < 4; j++)
                lb[j] = *(const float4*)(Wg + (size_t)brow[j] * DD + kk + bco[j]);
        }

        const uint32_t stg = sbase + (uint32_t)((kt & 1) * STG_H * 2);

#pragma unroll
        for (int ks = 0; ks < 32; ks += 16) {
            uint32_t af[2][4], bf[8][2];
#pragma unroll
            for (int mi = 0; mi < 2; mi++)
                ldsm4(af[mi], stg + (aoff[mi] + ks) * 2);
#pragma unroll
            for (int pi = 0; pi < 4; pi++) {
                uint32_t r[4];
                ldsm4(r, stg + (boff[pi] + ks) * 2);
                bf[2 * pi][0] = r[0]; bf[2 * pi][1] = r[1];
                bf[2 * pi + 1][0] = r[2]; bf[2 * pi + 1][1] = r[3];
            }
#pragma unroll
            for (int mi = 0; mi < 2; mi++)
#pragma unroll
                for (int ni = 0; ni < 8; ni++)
                    mma16816(acc[mi][ni], af[mi], bf[ni]);
        }

        if (kt < 15) {
            __half* dA = smh + ((kt + 1) & 1) * STG_H;
            __half* dB = dA + 128 * PADH;
#pragma unroll
            for (int j = 0; j < 2; j++) {
                __half* p = dA + arow[j] * PADH + aco[j];
                *(__half2*)(p)     = __floats2half2_rn(la[j].x, la[j].y);
                *(__half2*)(p + 2) = __floats2half2_rn(la[j].z, la[j].w);
            }
#pragma unroll
            for (int j = 0; j < 4; j++) {
                __half* p = dB + brow[j] * PADH + bco[j];
                *(__half2*)(p)     = __floats2half2_rn(lb[j].x, lb[j].y);
                *(__half2*)(p + 2) = __floats2half2_rn(lb[j].z, lb[j].w);
            }
        }
        __syncthreads();
    }

    // epilogue: bias + opt elu+1, write fp16
#pragma unroll
    for (int mi = 0; mi < 2; mi++) {
        const int row = m0 + wm * 32 + mi * 16 + g;
#pragma unroll
        for (int ni = 0; ni < 8; ni++) {
            const int col = n0 + wn * 64 + ni * 8 + tq * 2;
            const float b0 = bias[col], b1 = bias[col + 1];
            float v0 = acc[mi][ni][0] + b0;
            float v1 = acc[mi][ni][1] + b1;
            float v2 = acc[mi][ni][2] + b0;
            float v3 = acc[mi][ni][3] + b1;
            if (act) {
                v0 = (v0 > 0.f) ? (v0 + 1.f) : __expf(v0);
                v1 = (v1 > 0.f) ? (v1 + 1.f) : __expf(v1);
                v2 = (v2 > 0.f) ? (v2 + 1.f) : __expf(v2);
                v3 = (v3 > 0.f) ? (v3 + 1.f) : __expf(v3);
            }
            *(__half2*)(C + (size_t)row * DD + col)       = __floats2half2_rn(v0, v1);
            *(__half2*)(C + (size_t)(row + 8) * DD + col) = __floats2half2_rn(v2, v3);
        }
    }
}

// ===========================================================================
// KV reduce (fp16 tensor cores):
// per (bh, chunk): C[m][d] += sum_s V[s][m]*K[s][d] over 256 s-rows; z[d] too.
// Both operands via ldmatrix.x4.trans from [s][*] smem tiles.
// ===========================================================================
#define FPK 72
#define KVT_SMEM (2 * 256 * FPK * 2)   // 73728 bytes

__global__ void __launch_bounds__(256)
kv_reduce_f16_kernel(const __half* __restrict__ Kmat, const __half* __restrict__ Vmat)
{
    extern __shared__ __half smk[];
    __half* Ks = smk;                 // [256][FPK]
    __half* Vs = smk + 256 * FPK;
    __shared__ float zred[4][DHD];
    const uint32_t sbase = (uint32_t)__cvta_generic_to_shared(smk);

    const int bh = blockIdx.x;        // 0..31
    const int chunk = blockIdx.y;     // 0..31
    const int b = bh / HH, h = bh % HH;
    const int s0g = chunk * 256;

    const __half* Kbase = Kmat + (size_t)b * SS * DD + (size_t)s0g * DD + h * DHD;
    const __half* Vbase = Vmat + (size_t)b * SS * DD + (size_t)s0g * DD + h * DHD;

    const int tid = threadIdx.x;
    const int lane = tid & 31;
    const int wid = tid >> 5;
    const int wm = wid & 1;           // 2 m-warps * 32
    const int wn = wid >> 1;          // 4 d-warps * 16
    const int g = lane >> 2;
    const int tq = lane & 3;

    // load K,V chunk [256][64] fp16 -> smem
#pragma unroll
    for (int j = 0; j < 8; j++) {
        const int id = tid + 256 * j;
        const int row = id >> 3;
        const int c8 = (id & 7) * 8;
        *(uint4*)(Ks + row * FPK + c8) = *(const uint4*)(Kbase + (size_t)row * DD + c8);
        *(uint4*)(Vs + row * FPK + c8) = *(const uint4*)(Vbase + (size_t)row * DD + c8);
    }
    __syncthreads();

    // trans-ldmatrix offsets (in halves; s-step added in loop)
    // A (from V): row = s + (lane&7) + ((lane&16)>>1), col = m0 + (lane&8)
    uint32_t aoff[2];
#pragma unroll
    for (int mi = 0; mi < 2; mi++)
        aoff[mi] = (uint32_t)(256 * FPK) /* Vs base */
                 + ((lane & 7) + ((lane & 16) >> 1)) * FPK
                 + (wm * 32 + mi * 16 + (lane & 8));
    // B (from K): row = s + (lane&7) + (lane&8), col = n0 + ((lane&16)>>1)
    const uint32_t boff = ((lane & 7) + (lane & 8)) * FPK
                        + (wn * 16 + ((lane & 16) >> 1));

    float acc[2][2][4];
#pragma unroll
    for (int i = 0; i < 2; i++)
#pragma unroll
        for (int j = 0; j < 2; j++)
#pragma unroll
            for (int c = 0; c < 4; c++) acc[i][j][c] = 0.f;

#pragma unroll 4
    for (int s = 0; s < 256; s += 16) {
        uint32_t af[2][4], bt[4];
#pragma unroll
        for (int mi = 0; mi < 2; mi++)
            ldsm4t(af[mi], sbase + (aoff[mi] + s * FPK) * 2);
        ldsm4t(bt, sbase + (boff + s * FPK) * 2);
        uint32_t bf0[2] = {bt[0], bt[1]};
        uint32_t bf1[2] = {bt[2], bt[3]};
#pragma unroll
        for (int mi = 0; mi < 2; mi++) {
            mma16816(acc[mi][0], af[mi], bf0);
            mma16816(acc[mi][1], af[mi], bf1);
        }
    }

    // z partial: sum K over s
    {
        const int dcol = tid & 63;
        const int part = tid >> 6;
        float zs = 0.f;
#pragma unroll 8
        for (int i = 0; i < 64; i++)
            zs += __half2float(Ks[(part * 64 + i) * FPK + dcol]);
        zred[part][dcol] = zs;
    }
    __syncthreads();
    if (tid < DHD)
        g_z_part[((size_t)chunk * (BB * HH) + bh) * DHD + tid] =
            zred[0][tid] + zred[1][tid] + zred[2][tid] + zred[3][tid];

    // store kv partial [m][d]
    float* kvp = g_kv_part + ((size_t)chunk * (BB * HH) + bh) * DHD * DHD;
#pragma unroll
    for (int mi = 0; mi < 2; mi++) {
        const int m = wm * 32 + mi * 16 + g;
#pragma unroll
        for (int ni = 0; ni < 2; ni++) {
            const int d = wn * 16 + ni * 8 + tq * 2;
            *(float2*)&kvp[m * DHD + d]       = make_float2(acc[mi][ni][0], acc[mi][ni][1]);
            *(float2*)&kvp[(m + 8) * DHD + d] = make_float2(acc[mi][ni][2], acc[mi][ni][3]);
        }
    }
}

// ===========================================================================
// Finalize: sum partials -> dout (kv [d][m], z) + fp16 g_kvT [m][d]
// ===========================================================================
__global__ void __launch_bounds__(256)
kv_finalize_kernel(float* __restrict__ dout, int write_out)
{
    const int idx = blockIdx.x * blockDim.x + threadIdx.x;
    if (idx < NKV) {
        float s = 0.f;
#pragma unroll
        for (int c = 0; c < KVC; c++) s += g_kv_part[(size_t)c * NKV + idx];
        const int bh = idx >> 12;
        const int rem = idx & 4095;     // m*64 + d
        const int m = rem >> 6;
        const int d = rem & 63;
        g_kvT[bh * 4096 + rem] = __float2half(s);
        if (write_out) dout[OFF_KV + bh * 4096 + d * 64 + m] = s;
    } else if (idx < NKV + NZ) {
        const int id2 = idx - NKV;
        float s = 0.f;
#pragma unroll
        for (int c = 0; c < KVC; c++) s += g_z_part[(size_t)c * NZ + id2];
        g_z[id2] = s;
        if (write_out) dout[OFF_Z + id2] = s;
    }
}

// ===========================================================================
// Fused attention + output GEMM (512 threads, ldmatrix):
//   out[m,n] = sum_h ((Q_h[m,:] @ kv_h) / (Q_h[m,:].z_h + eps)) @ Wo_h^T + bo
// Q now fp16 in global.
// ===========================================================================
#define FP 72

#define QH_OFF   0
#define ATT_OFF  18432
#define KV_OFF   36864
#define WH_OFF   46080
#define DEN_OFF  82944
#define ZF_OFF   83456
#define FUSED_SMEM 83712

__global__ void __launch_bounds__(512, 1)
gemm_out_fused_kernel(const __half* __restrict__ Q, const float* __restrict__ Wo,
                      const float* __restrict__ bo, float* __restrict__ out)
{
    extern __shared__ char smb[];
    __half* Qh   = (__half*)(smb + QH_OFF);
    __half* ATTh = (__half*)(smb + ATT_OFF);
    __half* KVh  = (__half*)(smb + KV_OFF);
    __half* Wh   = (__half*)(smb + WH_OFF);
    float* invden = (float*)(smb + DEN_OFF);
    float* zf     = (float*)(smb + ZF_OFF);
    const uint32_t sbase = (uint32_t)__cvta_generic_to_shared(smb);

    const int tid  = threadIdx.x;
    const int lane = tid & 31;
    const int wid  = tid >> 5;
    const int wm   = wid & 3;
    const int wn   = wid >> 2;
    const int g    = lane >> 2;
    const int tq   = lane & 3;
    const int m0   = blockIdx.y * 128;
    const int n0   = blockIdx.x * 256;
    const int bidx = m0 >> 13;

    uint32_t qoff[2], attoff[2], kvoff, woff[4];
#pragma unroll
    for (int mi = 0; mi < 2; mi++) {
        const uint32_t r = wm * 32 + mi * 16 + (lane & 15);
        const uint32_t kh = (lane >> 4) << 3;
        qoff[mi]   = (uint32_t)(QH_OFF / 2)  + r * FP + kh;
        attoff[mi] = (uint32_t)(ATT_OFF / 2) + r * FP + kh;
    }
    kvoff = (uint32_t)(KV_OFF / 2) + (wn * 16 + (lane & 7) + ((lane & 16) >> 1)) * FP + (lane & 8);
#pragma unroll
    for (int pi = 0; pi < 4; pi++)
        woff[pi] = (uint32_t)(WH_OFF / 2) + (wn * 64 + pi * 16 + (lane & 7) + ((lane & 16) >> 1)) * FP + (lane & 8);

    float acc[2][8][4];
#pragma unroll
    for (int i = 0; i < 2; i++)
#pragma unroll
        for (int j = 0; j < 8; j++)
#pragma unroll
            for (int c = 0; c < 4; c++) acc[i][j][c] = 0.f;

    for (int h = 0; h < HH; h++) {
        const int bh = bidx * HH + h;
        __syncthreads();

        // --- Q tile [128][64] fp16: direct copy ---
#pragma unroll
        for (int j = 0; j < 2; j++) {
            const int id = tid + 512 * j;
            const int row = id >> 3;
            const int c8 = (id & 7) * 8;
            *(uint4*)(Qh + row * FP + c8) =
                *(const uint4*)(Q + (size_t)(m0 + row) * DD + h * 64 + c8);
        }
        // --- kv_h [m][d] fp16 ---
        {
            const uint32_t* src = (const uint32_t*)(g_kvT + (size_t)bh * 4096);
            uint32_t* dst = (uint32_t*)KVh;
#pragma unroll
            for (int j = 0; j < 4; j++) {
                const int w = tid + 512 * j;
                const int m = w >> 5;
                const int dw = w & 31;
                dst[m * (FP / 2) + dw] = src[w];
            }
        }
        if (tid < DHD) zf[tid] = g_z[bh * DHD + tid];
        // --- Wo tile [256][64] fp32 -> fp16 ---
#pragma unroll
        for (int j = 0; j < 8; j++) {
            const int id = tid + 512 * j;
            const int row = id >> 4;
            const int c4 = (id & 15) * 4;
            float4 wv = *(const float4*)(Wo + (size_t)(n0 + row) * DD + h * 64 + c4);
            __half* p = Wh + row * FP + c4;
            *(__half2*)(p)     = __floats2half2_rn(wv.x, wv.y);
            *(__half2*)(p + 2) = __floats2half2_rn(wv.z, wv.w);
        }
        __syncthreads();

        // --- den: 4 threads per row ---
        {
            const int r = tid >> 2;
            const int o = tid & 3;
            float s = 0.f;
            const __half2* qrow = (const __half2*)(Qh + r * FP) + o * 8;
#pragma unroll
            for (int i = 0; i < 8; i++) {
                float2 qf = __half22float2(qrow[i]);
                const int d = o * 16 + i * 2;
                s = fmaf(qf.x, zf[d], s);
                s = fmaf(qf.y, zf[d + 1], s);
            }
            s += __shfl_xor_sync(0xffffffffu, s, 1);
            s += __shfl_xor_sync(0xffffffffu, s, 2);
            if (o == 0) invden[r] = 1.0f / (s + EPSF);
        }
        __syncthreads();

        // --- att = Q @ kv, scaled ---
        {
            float aacc[2][2][4];
#pragma unroll
            for (int i = 0; i < 2; i++)
#pragma unroll
                for (int j = 0; j < 2; j++)
#pragma unroll
                    for (int c = 0; c < 4; c++) aacc[i][j][c] = 0.f;

#pragma unroll
            for (int kt = 0; kt < 4; kt++) {
                uint32_t af[2][4], bf[2][2];
#pragma unroll
                for (int mi = 0; mi < 2; mi++)
                    ldsm4(af[mi], sbase + (qoff[mi] + kt * 16) * 2);
                {
                    uint32_t r[4];
                    ldsm4(r, sbase + (kvoff + kt * 16) * 2);
                    bf[0][0] = r[0]; bf[0][1] = r[1];
                    bf[1][0] = r[2]; bf[1][1] = r[3];
                }
#pragma unroll
                for (int mi = 0; mi < 2; mi++)
#pragma unroll
                    for (int ni = 0; ni < 2; ni++)
                        mma16816(aacc[mi][ni], af[mi], bf[ni]);
            }
#pragma unroll
            for (int mi = 0; mi < 2; mi++) {
                const int r = wm * 32 + mi * 16 + g;
                const float i0 = invden[r];
                const float i1 = invden[r + 8];
#pragma unroll
                for (int ni = 0; ni < 2; ni++) {
                    const int c = wn * 16 + ni * 8 + 2 * tq;
                    *(__half2*)(ATTh + r * FP + c) =
                        __floats2half2_rn(aacc[mi][ni][0] * i0, aacc[mi][ni][1] * i0);
                    *(__half2*)(ATTh + (r + 8) * FP + c) =
                        __floats2half2_rn(aacc[mi][ni][2] * i1, aacc[mi][ni][3] * i1);
                }
            }
        }
        __syncthreads();

        // --- acc += att @ Wo_h^T ---
#pragma unroll
        for (int kt = 0; kt < 4; kt++) {
            uint32_t af[2][4], bf[8][2];
#pragma unroll
            for (int mi = 0; mi < 2; mi++)
                ldsm4(af[mi], sbase + (attoff[mi] + kt * 16) * 2);
#pragma unroll
            for (int pi = 0; pi < 4; pi++) {
                uint32_t r[4];
                ldsm4(r, sbase + (woff[pi] + kt * 16) * 2);
                bf[2 * pi][0] = r[0]; bf[2 * pi][1] = r[1];
                bf[2 * pi + 1][0] = r[2]; bf[2 * pi + 1][1] = r[3];
            }
#pragma unroll
            for (int mi = 0; mi < 2; mi++)
#pragma unroll
                for (int ni = 0; ni < 8; ni++)
                    mma16816(acc[mi][ni], af[mi], bf[ni]);
        }
    }

    // epilogue: + bo
#pragma unroll
    for (int mi = 0; mi < 2; mi++) {
        const int row = m0 + wm * 32 + mi * 16 + g;
#pragma unroll
        for (int ni = 0; ni < 8; ni++) {
            const int col = n0 + wn * 64 + ni * 8 + tq * 2;
            const float b0 = bo[col], b1 = bo[col + 1];
            *(float2*)(out + (size_t)row * DD + col) =
                make_float2(acc[mi][ni][0] + b0, acc[mi][ni][1] + b1);
            *(float2*)(out + (size_t)(row + 8) * DD + col) =
                make_float2(acc[mi][ni][2] + b0, acc[mi][ni][3] + b1);
        }
    }
}

// ===========================================================================
// Launch
// ===========================================================================
extern "C" void kernel_launch(void* const* d_in, const int* in_sizes, int n_in,
                              void* d_out, int out_size)
{
    const float* q  = (const float*)d_in[0];
    const float* k  = (const float*)d_in[1];
    const float* v  = (const float*)d_in[2];
    const float* Wq = (const float*)d_in[3];
    const float* bq = (const float*)d_in[4];
    const float* Wk = (const float*)d_in[5];
    const float* bk = (const float*)d_in[6];
    const float* Wv = (const float*)d_in[7];
    const float* bv = (const float*)d_in[8];
    const float* Wo = (const float*)d_in[9];
    const float* bo = (const float*)d_in[10];
    float* out = (float*)d_out;

    __half *gQ, *gK, *gV;
    cudaGetSymbolAddress((void**)&gQ, g_Q);
    cudaGetSymbolAddress((void**)&gK, g_K);
    cudaGetSymbolAddress((void**)&gV, g_V);

    const int write_extra = ((size_t)out_size >= OFF_Z + NZ) ? 1 : 0;

    const int gemm_smem = 2 * STG_H * 2;   // 61440 bytes
    cudaFuncSetAttribute(gemm_f16_kernel,
                         cudaFuncAttributeMaxDynamicSharedMemorySize, gemm_smem);
    cudaFuncSetAttribute(gemm_out_fused_kernel,
                         cudaFuncAttributeMaxDynamicSharedMemorySize, FUSED_SMEM);
    cudaFuncSetAttribute(kv_reduce_f16_kernel,
                         cudaFuncAttributeMaxDynamicSharedMemorySize, KVT_SMEM);

    dim3 gemm_grid(DD / 256, MR / 128);     // (2, 256)
    gemm_f16_kernel<<<gemm_grid, 512, gemm_smem>>>(k, Wk, bk, gK, 1);
    gemm_f16_kernel<<<gemm_grid, 512, gemm_smem>>>(v, Wv, bv, gV, 0);
    gemm_f16_kernel<<<gemm_grid, 512, gemm_smem>>>(q, Wq, bq, gQ, 1);

    dim3 kv_grid(BB * HH, KVC);             // (32, 32)
    kv_reduce_f16_kernel<<<kv_grid, 256, KVT_SMEM>>>(gK, gV);

    const int fin_total = NKV + NZ;
    kv_finalize_kernel<<<(fin_total + 255) / 256, 256>>>(out, write_extra);

    gemm_out_fused_kernel<<<gemm_grid, 512, FUSED_SMEM>>>(gQ, Wo, bo, out);
}

// round 14
// speedup vs baseline: 4.9592x; 1.2460x over previous
#include <cuda_runtime.h>
#include <cuda_fp16.h>
#include <cstdint>

// Problem constants
#define BB 4
#define SS 8192
#define DD 512
#define HH 8
#define DHD 64
#define MR (BB*SS)          // 32768 rows
#define EPSF 1e-6f
#define KVC 32

// Output layout: out [B,S,D], k_v [B,H,DH,DH], z [B,H,DH]
#define OFF_KV ((size_t)MR*DD)
#define NKV (BB*HH*DHD*DHD)
#define OFF_Z (OFF_KV + NKV)
#define NZ (BB*HH*DHD)

// Scratch (device globals)
__device__ __half g_qh[(size_t)MR*DD];   // fp16 inputs
__device__ __half g_kh[(size_t)MR*DD];
__device__ __half g_vh[(size_t)MR*DD];
__device__ __half g_Wh4[(size_t)4*DD*DD]; // fp16 weights: Wq,Wk,Wv,Wo
__device__ __half g_Q[(size_t)MR*DD];    // fp16 projected
__device__ __half g_K[(size_t)MR*DD];
__device__ __half g_V[(size_t)MR*DD];
__device__ float g_kv_part[(size_t)KVC*BB*HH*DHD*DHD];
__device__ float g_z_part[(size_t)KVC*BB*HH*DHD];
__device__ __half g_kvT[NKV];
__device__ float g_z[NZ];

// ---------------------------------------------------------------------------
__device__ __forceinline__ void mma16816(float* c, const uint32_t* a, const uint32_t* b) {
    asm volatile(
        "mma.sync.aligned.m16n8k16.row.col.f32.f16.f16.f32 "
        "{%0,%1,%2,%3}, {%4,%5,%6,%7}, {%8,%9}, {%0,%1,%2,%3};\n"
        : "+f"(c[0]), "+f"(c[1]), "+f"(c[2]), "+f"(c[3])
        : "r"(a[0]), "r"(a[1]), "r"(a[2]), "r"(a[3]), "r"(b[0]), "r"(b[1]));
}

__device__ __forceinline__ void ldsm4(uint32_t* r, uint32_t addr) {
    asm volatile("ldmatrix.sync.aligned.m8n8.x4.shared.b16 {%0,%1,%2,%3}, [%4];"
        : "=r"(r[0]), "=r"(r[1]), "=r"(r[2]), "=r"(r[3]) : "r"(addr));
}

__device__ __forceinline__ void ldsm4t(uint32_t* r, uint32_t addr) {
    asm volatile("ldmatrix.sync.aligned.m8n8.x4.trans.shared.b16 {%0,%1,%2,%3}, [%4];"
        : "=r"(r[0]), "=r"(r[1]), "=r"(r[2]), "=r"(r[3]) : "r"(addr));
}

__device__ __forceinline__ void cpasync16(uint32_t saddr, const void* gptr) {
    asm volatile("cp.async.cg.shared.global [%0], [%1], 16;" :: "r"(saddr), "l"(gptr) : "memory");
}
#define CP_COMMIT() asm volatile("cp.async.commit_group;" ::: "memory")
#define CP_WAIT1()  asm volatile("cp.async.wait_group 1;" ::: "memory")

// ===========================================================================
// Conversion kernels
// ===========================================================================
__global__ void __launch_bounds__(256)
cvt_inputs_kernel(const float* __restrict__ q, const float* __restrict__ k,
                  const float* __restrict__ v)
{
    const size_t N4 = (size_t)MR * DD / 4;
    const size_t stride = (size_t)gridDim.x * blockDim.x;
    for (size_t i = (size_t)blockIdx.x * blockDim.x + threadIdx.x; i < N4; i += stride) {
        float4 a = ((const float4*)q)[i];
        float4 b = ((const float4*)k)[i];
        float4 c = ((const float4*)v)[i];
        __half2 r0 = __floats2half2_rn(a.x, a.y), r1 = __floats2half2_rn(a.z, a.w);
        ((uint2*)g_qh)[i] = make_uint2(*(uint32_t*)&r0, *(uint32_t*)&r1);
        r0 = __floats2half2_rn(b.x, b.y); r1 = __floats2half2_rn(b.z, b.w);
        ((uint2*)g_kh)[i] = make_uint2(*(uint32_t*)&r0, *(uint32_t*)&r1);
        r0 = __floats2half2_rn(c.x, c.y); r1 = __floats2half2_rn(c.z, c.w);
        ((uint2*)g_vh)[i] = make_uint2(*(uint32_t*)&r0, *(uint32_t*)&r1);
    }
}

__global__ void __launch_bounds__(256)
cvt_weights_kernel(const float* __restrict__ Wq, const float* __restrict__ Wk,
                   const float* __restrict__ Wv, const float* __restrict__ Wo)
{
    const int NW = DD * DD / 4;   // float4 per weight
    const int i = blockIdx.x * blockDim.x + threadIdx.x;
    const float* srcs[4] = {Wq, Wk, Wv, Wo};
    if (i < NW) {
#pragma unroll
        for (int w = 0; w < 4; w++) {
            float4 a = ((const float4*)srcs[w])[i];
            __half2 r0 = __floats2half2_rn(a.x, a.y), r1 = __floats2half2_rn(a.z, a.w);
            ((uint2*)(g_Wh4 + (size_t)w * DD * DD))[i] = make_uint2(*(uint32_t*)&r0, *(uint32_t*)&r1);
        }
    }
}

// ===========================================================================
// fp16 GEMM with cp.async 3-stage pipeline:
// C[M,512] = A[M,512] @ W[512,512]^T + bias, opt elu+1. fp16 in/out.
// BM=128, BN=256, BK=32, 512 threads (16 warps 4x4), warp tile 32x64.
// ===========================================================================
#define PADH 40
#define ROWB (PADH * 2)                 // 80 bytes per padded row
#define STG_B ((128 + 256) * ROWB)      // 30720 bytes per stage
#define GEMM_SMEM (3 * STG_B)           // 92160

__global__ void __launch_bounds__(512, 1)
gemm_cp_kernel(const __half* __restrict__ A, const __half* __restrict__ W,
               const float* __restrict__ bias, __half* __restrict__ C, int act)
{
    extern __shared__ char smc[];
    const uint32_t sbase = (uint32_t)__cvta_generic_to_shared(smc);

    const int tid  = threadIdx.x;
    const int lane = tid & 31;
    const int wid  = tid >> 5;
    const int wm   = wid & 3;
    const int wn   = wid >> 2;
    const int g    = lane >> 2;
    const int tq   = lane & 3;
    const int m0   = blockIdx.y * 128;
    const int n0   = blockIdx.x * 256;

    float acc[2][8][4];
#pragma unroll
    for (int i = 0; i < 2; i++)
#pragma unroll
        for (int j = 0; j < 8; j++)
#pragma unroll
            for (int c = 0; c < 4; c++) acc[i][j][c] = 0.f;

    // copy maps (16B chunks): A 512 chunks, B 1024 chunks
    const int ar = tid >> 2, ac = tid & 3;
    const int br0 = tid >> 2, bc0 = tid & 3;
    const int br1 = (tid + 512) >> 2, bc1 = (tid + 512) & 3;

    const __half* Ag = A + (size_t)m0 * DD;
    const __half* Wg = W + (size_t)n0 * DD;

    // ldmatrix offsets (halves)
    uint32_t aoff[2], boff[4];
#pragma unroll
    for (int mi = 0; mi < 2; mi++)
        aoff[mi] = (wm * 32 + mi * 16 + (lane & 15)) * PADH + ((lane >> 4) << 3);
#pragma unroll
    for (int pi = 0; pi < 4; pi++)
        boff[pi] = (128 + wn * 64 + pi * 16 + (lane & 7) + ((lane & 16) >> 1)) * PADH + (lane & 8);

    // prologue: issue stages 0,1 (ktiles 0,1)
#pragma unroll
    for (int p = 0; p < 2; p++) {
        const uint32_t st = sbase + p * STG_B;
        cpasync16(st + ar * ROWB + ac * 16, Ag + (size_t)ar * DD + p * 32 + ac * 8);
        cpasync16(st + 128 * ROWB + br0 * ROWB + bc0 * 16, Wg + (size_t)br0 * DD + p * 32 + bc0 * 8);
        cpasync16(st + 128 * ROWB + br1 * ROWB + bc1 * 16, Wg + (size_t)br1 * DD + p * 32 + bc1 * 8);
        CP_COMMIT();
    }

    int stage = 0;
    for (int kt = 0; kt < 16; kt++) {
        CP_WAIT1();
        __syncthreads();

        const uint32_t stg = sbase + stage * STG_B;
#pragma unroll
        for (int ks = 0; ks < 32; ks += 16) {
            uint32_t af[2][4], bf[8][2];
#pragma unroll
            for (int mi = 0; mi < 2; mi++)
                ldsm4(af[mi], stg + (aoff[mi] + ks) * 2);
#pragma unroll
            for (int pi = 0; pi < 4; pi++) {
                uint32_t r[4];
                ldsm4(r, stg + (boff[pi] + ks) * 2);
                bf[2 * pi][0] = r[0]; bf[2 * pi][1] = r[1];
                bf[2 * pi + 1][0] = r[2]; bf[2 * pi + 1][1] = r[3];
            }
#pragma unroll
            for (int mi = 0; mi < 2; mi++)
#pragma unroll
                for (int ni = 0; ni < 8; ni++)
                    mma16816(acc[mi][ni], af[mi], bf[ni]);
        }

        // issue ktile kt+2 into the stage freed last iteration
        if (kt + 2 < 16) {
            const int ns = (stage + 2) % 3;
            const uint32_t st = sbase + ns * STG_B;
            const int kk = (kt + 2) * 32;
            cpasync16(st + ar * ROWB + ac * 16, Ag + (size_t)ar * DD + kk + ac * 8);
            cpasync16(st + 128 * ROWB + br0 * ROWB + bc0 * 16, Wg + (size_t)br0 * DD + kk + bc0 * 8);
            cpasync16(st + 128 * ROWB + br1 * ROWB + bc1 * 16, Wg + (size_t)br1 * DD + kk + bc1 * 8);
        }
        CP_COMMIT();
        stage = (stage + 1) % 3;
    }

    // epilogue
#pragma unroll
    for (int mi = 0; mi < 2; mi++) {
        const int row = m0 + wm * 32 + mi * 16 + g;
#pragma unroll
        for (int ni = 0; ni < 8; ni++) {
            const int col = n0 + wn * 64 + ni * 8 + tq * 2;
            const float b0 = bias[col], b1 = bias[col + 1];
            float v0 = acc[mi][ni][0] + b0;
            float v1 = acc[mi][ni][1] + b1;
            float v2 = acc[mi][ni][2] + b0;
            float v3 = acc[mi][ni][3] + b1;
            if (act) {
                v0 = (v0 > 0.f) ? (v0 + 1.f) : __expf(v0);
                v1 = (v1 > 0.f) ? (v1 + 1.f) : __expf(v1);
                v2 = (v2 > 0.f) ? (v2 + 1.f) : __expf(v2);
                v3 = (v3 > 0.f) ? (v3 + 1.f) : __expf(v3);
            }
            *(__half2*)(C + (size_t)row * DD + col)       = __floats2half2_rn(v0, v1);
            *(__half2*)(C + (size_t)(row + 8) * DD + col) = __floats2half2_rn(v2, v3);
        }
    }
}

// ===========================================================================
// KV reduce (fp16 mma.sync, trans ldmatrix)
// ===========================================================================
#define FPK 72
#define KVT_SMEM (2 * 256 * FPK * 2)

__global__ void __launch_bounds__(256)
kv_reduce_f16_kernel(const __half* __restrict__ Kmat, const __half* __restrict__ Vmat)
{
    extern __shared__ __half smk[];
    __half* Ks = smk;
    __half* Vs = smk + 256 * FPK;
    __shared__ float zred[4][DHD];
    const uint32_t sbase = (uint32_t)__cvta_generic_to_shared(smk);

    const int bh = blockIdx.x;
    const int chunk = blockIdx.y;
    const int b = bh / HH, h = bh % HH;
    const int s0g = chunk * 256;

    const __half* Kbase = Kmat + (size_t)b * SS * DD + (size_t)s0g * DD + h * DHD;
    const __half* Vbase = Vmat + (size_t)b * SS * DD + (size_t)s0g * DD + h * DHD;

    const int tid = threadIdx.x;
    const int lane = tid & 31;
    const int wid = tid >> 5;
    const int wm = wid & 1;
    const int wn = wid >> 1;
    const int g = lane >> 2;
    const int tq = lane & 3;

#pragma unroll
    for (int j = 0; j < 8; j++) {
        const int id = tid + 256 * j;
        const int row = id >> 3;
        const int c8 = (id & 7) * 8;
        *(uint4*)(Ks + row * FPK + c8) = *(const uint4*)(Kbase + (size_t)row * DD + c8);
        *(uint4*)(Vs + row * FPK + c8) = *(const uint4*)(Vbase + (size_t)row * DD + c8);
    }
    __syncthreads();

    uint32_t aoff[2];
#pragma unroll
    for (int mi = 0; mi < 2; mi++)
        aoff[mi] = (uint32_t)(256 * FPK)
                 + ((lane & 7) + ((lane & 16) >> 1)) * FPK
                 + (wm * 32 + mi * 16 + (lane & 8));
    const uint32_t boff = ((lane & 7) + (lane & 8)) * FPK
                        + (wn * 16 + ((lane & 16) >> 1));

    float acc[2][2][4];
#pragma unroll
    for (int i = 0; i < 2; i++)
#pragma unroll
        for (int j = 0; j < 2; j++)
#pragma unroll
            for (int c = 0; c < 4; c++) acc[i][j][c] = 0.f;

#pragma unroll 4
    for (int s = 0; s < 256; s += 16) {
        uint32_t af[2][4], bt[4];
#pragma unroll
        for (int mi = 0; mi < 2; mi++)
            ldsm4t(af[mi], sbase + (aoff[mi] + s * FPK) * 2);
        ldsm4t(bt, sbase + (boff + s * FPK) * 2);
        uint32_t bf0[2] = {bt[0], bt[1]};
        uint32_t bf1[2] = {bt[2], bt[3]};
#pragma unroll
        for (int mi = 0; mi < 2; mi++) {
            mma16816(acc[mi][0], af[mi], bf0);
            mma16816(acc[mi][1], af[mi], bf1);
        }
    }

    {
        const int dcol = tid & 63;
        const int part = tid >> 6;
        float zs = 0.f;
#pragma unroll 8
        for (int i = 0; i < 64; i++)
            zs += __half2float(Ks[(part * 64 + i) * FPK + dcol]);
        zred[part][dcol] = zs;
    }
    __syncthreads();
    if (tid < DHD)
        g_z_part[((size_t)chunk * (BB * HH) + bh) * DHD + tid] =
            zred[0][tid] + zred[1][tid] + zred[2][tid] + zred[3][tid];

    float* kvp = g_kv_part + ((size_t)chunk * (BB * HH) + bh) * DHD * DHD;
#pragma unroll
    for (int mi = 0; mi < 2; mi++) {
        const int m = wm * 32 + mi * 16 + g;
#pragma unroll
        for (int ni = 0; ni < 2; ni++) {
            const int d = wn * 16 + ni * 8 + tq * 2;
            *(float2*)&kvp[m * DHD + d]       = make_float2(acc[mi][ni][0], acc[mi][ni][1]);
            *(float2*)&kvp[(m + 8) * DHD + d] = make_float2(acc[mi][ni][2], acc[mi][ni][3]);
        }
    }
}

// ===========================================================================
// Finalize
// ===========================================================================
__global__ void __launch_bounds__(256)
kv_finalize_kernel(float* __restrict__ dout, int write_out)
{
    const int idx = blockIdx.x * blockDim.x + threadIdx.x;
    if (idx < NKV) {
        float s = 0.f;
#pragma unroll
        for (int c = 0; c < KVC; c++) s += g_kv_part[(size_t)c * NKV + idx];
        const int bh = idx >> 12;
        const int rem = idx & 4095;     // m*64 + d
        const int m = rem >> 6;
        const int d = rem & 63;
        g_kvT[bh * 4096 + rem] = __float2half(s);
        if (write_out) dout[OFF_KV + bh * 4096 + d * 64 + m] = s;
    } else if (idx < NKV + NZ) {
        const int id2 = idx - NKV;
        float s = 0.f;
#pragma unroll
        for (int c = 0; c < KVC; c++) s += g_z_part[(size_t)c * NZ + id2];
        g_z[id2] = s;
        if (write_out) dout[OFF_Z + id2] = s;
    }
}

// ===========================================================================
// Fused attention + output GEMM (mma.sync, 512 threads); Wo fp16
// ===========================================================================
#define FP 72

#define QH_OFF   0
#define ATT_OFF  18432
#define KV_OFF   36864
#define WH_OFF   46080
#define DEN_OFF  82944
#define ZF_OFF   83456
#define FUSED_SMEM 83712

__global__ void __launch_bounds__(512, 1)
gemm_out_fused_kernel(const __half* __restrict__ Q, const __half* __restrict__ Woh,
                      const float* __restrict__ bo, float* __restrict__ out)
{
    extern __shared__ char smb[];
    __half* Qh   = (__half*)(smb + QH_OFF);
    __half* ATTh = (__half*)(smb + ATT_OFF);
    __half* KVh  = (__half*)(smb + KV_OFF);
    __half* Wh   = (__half*)(smb + WH_OFF);
    float* invden = (float*)(smb + DEN_OFF);
    float* zf     = (float*)(smb + ZF_OFF);
    const uint32_t sbase = (uint32_t)__cvta_generic_to_shared(smb);

    const int tid  = threadIdx.x;
    const int lane = tid & 31;
    const int wid  = tid >> 5;
    const int wm   = wid & 3;
    const int wn   = wid >> 2;
    const int g    = lane >> 2;
    const int tq   = lane & 3;
    const int m0   = blockIdx.y * 128;
    const int n0   = blockIdx.x * 256;
    const int bidx = m0 >> 13;

    uint32_t qoff[2], attoff[2], kvoff, woff[4];
#pragma unroll
    for (int mi = 0; mi < 2; mi++) {
        const uint32_t r = wm * 32 + mi * 16 + (lane & 15);
        const uint32_t kh = (lane >> 4) << 3;
        qoff[mi]   = (uint32_t)(QH_OFF / 2)  + r * FP + kh;
        attoff[mi] = (uint32_t)(ATT_OFF / 2) + r * FP + kh;
    }
    kvoff = (uint32_t)(KV_OFF / 2) + (wn * 16 + (lane & 7) + ((lane & 16) >> 1)) * FP + (lane & 8);
#pragma unroll
    for (int pi = 0; pi < 4; pi++)
        woff[pi] = (uint32_t)(WH_OFF / 2) + (wn * 64 + pi * 16 + (lane & 7) + ((lane & 16) >> 1)) * FP + (lane & 8);

    float acc[2][8][4];
#pragma unroll
    for (int i = 0; i < 2; i++)
#pragma unroll
        for (int j = 0; j < 8; j++)
#pragma unroll
            for (int c = 0; c < 4; c++) acc[i][j][c] = 0.f;

    for (int h = 0; h < HH; h++) {
        const int bh = bidx * HH + h;
        __syncthreads();

        // Q tile [128][64] fp16 copy
#pragma unroll
        for (int j = 0; j < 2; j++) {
            const int id = tid + 512 * j;
            const int row = id >> 3;
            const int c8 = (id & 7) * 8;
            *(uint4*)(Qh + row * FP + c8) =
                *(const uint4*)(Q + (size_t)(m0 + row) * DD + h * 64 + c8);
        }
        // kv tile
        {
            const uint32_t* src = (const uint32_t*)(g_kvT + (size_t)bh * 4096);
            uint32_t* dst = (uint32_t*)KVh;
#pragma unroll
            for (int j = 0; j < 4; j++) {
                const int w = tid + 512 * j;
                const int m = w >> 5;
                const int dw = w & 31;
                dst[m * (FP / 2) + dw] = src[w];
            }
        }
        if (tid < DHD) zf[tid] = g_z[bh * DHD + tid];
        // Wo tile [256][64] fp16 copy
#pragma unroll
        for (int j = 0; j < 4; j++) {
            const int id = tid + 512 * j;
            const int row = id >> 3;
            const int c8 = (id & 7) * 8;
            *(uint4*)(Wh + row * FP + c8) =
                *(const uint4*)(Woh + (size_t)(n0 + row) * DD + h * 64 + c8);
        }
        __syncthreads();

        // den
        {
            const int r = tid >> 2;
            const int o = tid & 3;
            float s = 0.f;
            const __half2* qrow = (const __half2*)(Qh + r * FP) + o * 8;
#pragma unroll
            for (int i = 0; i < 8; i++) {
                float2 qf = __half22float2(qrow[i]);
                const int d = o * 16 + i * 2;
                s = fmaf(qf.x, zf[d], s);
                s = fmaf(qf.y, zf[d + 1], s);
            }
            s += __shfl_xor_sync(0xffffffffu, s, 1);
            s += __shfl_xor_sync(0xffffffffu, s, 2);
            if (o == 0) invden[r] = 1.0f / (s + EPSF);
        }
        __syncthreads();

        // att = Q @ kv, scaled
        {
            float aacc[2][2][4];
#pragma unroll
            for (int i = 0; i < 2; i++)
#pragma unroll
                for (int j = 0; j < 2; j++)
#pragma unroll
                    for (int c = 0; c < 4; c++) aacc[i][j][c] = 0.f;

#pragma unroll
            for (int kt = 0; kt < 4; kt++) {
                uint32_t af[2][4], bf[2][2];
#pragma unroll
                for (int mi = 0; mi < 2; mi++)
                    ldsm4(af[mi], sbase + (qoff[mi] + kt * 16) * 2);
                {
                    uint32_t r[4];
                    ldsm4(r, sbase + (kvoff + kt * 16) * 2);
                    bf[0][0] = r[0]; bf[0][1] = r[1];
                    bf[1][0] = r[2]; bf[1][1] = r[3];
                }
#pragma unroll
                for (int mi = 0; mi < 2; mi++)
#pragma unroll
                    for (int ni = 0; ni < 2; ni++)
                        mma16816(aacc[mi][ni], af[mi], bf[ni]);
            }
#pragma unroll
            for (int mi = 0; mi < 2; mi++) {
                const int r = wm * 32 + mi * 16 + g;
                const float i0 = invden[r];
                const float i1 = invden[r + 8];
#pragma unroll
                for (int ni = 0; ni < 2; ni++) {
                    const int c = wn * 16 + ni * 8 + 2 * tq;
                    *(__half2*)(ATTh + r * FP + c) =
                        __floats2half2_rn(aacc[mi][ni][0] * i0, aacc[mi][ni][1] * i0);
                    *(__half2*)(ATTh + (r + 8) * FP + c) =
                        __floats2half2_rn(aacc[mi][ni][2] * i1, aacc[mi][ni][3] * i1);
                }
            }
        }
        __syncthreads();

        // acc += att @ Wo_h^T
#pragma unroll
        for (int kt = 0; kt < 4; kt++) {
            uint32_t af[2][4], bf[8][2];
#pragma unroll
            for (int mi = 0; mi < 2; mi++)
                ldsm4(af[mi], sbase + (attoff[mi] + kt * 16) * 2);
#pragma unroll
            for (int pi = 0; pi < 4; pi++) {
                uint32_t r[4];
                ldsm4(r, sbase + (woff[pi] + kt * 16) * 2);
                bf[2 * pi][0] = r[0]; bf[2 * pi][1] = r[1];
                bf[2 * pi + 1][0] = r[2]; bf[2 * pi + 1][1] = r[3];
            }
#pragma unroll
            for (int mi = 0; mi < 2; mi++)
#pragma unroll
                for (int ni = 0; ni < 8; ni++)
                    mma16816(acc[mi][ni], af[mi], bf[ni]);
        }
    }

    // epilogue: + bo
#pragma unroll
    for (int mi = 0; mi < 2; mi++) {
        const int row = m0 + wm * 32 + mi * 16 + g;
#pragma unroll
        for (int ni = 0; ni < 8; ni++) {
            const int col = n0 + wn * 64 + ni * 8 + tq * 2;
            const float b0 = bo[col], b1 = bo[col + 1];
            *(float2*)(out + (size_t)row * DD + col) =
                make_float2(acc[mi][ni][0] + b0, acc[mi][ni][1] + b1);
            *(float2*)(out + (size_t)(row + 8) * DD + col) =
                make_float2(acc[mi][ni][2] + b0, acc[mi][ni][3] + b1);
        }
    }
}

// ===========================================================================
// Launch
// ===========================================================================
extern "C" void kernel_launch(void* const* d_in, const int* in_sizes, int n_in,
                              void* d_out, int out_size)
{
    const float* q  = (const float*)d_in[0];
    const float* k  = (const float*)d_in[1];
    const float* v  = (const float*)d_in[2];
    const float* Wq = (const float*)d_in[3];
    const float* bq = (const float*)d_in[4];
    const float* Wk = (const float*)d_in[5];
    const float* bk = (const float*)d_in[6];
    const float* Wv = (const float*)d_in[7];
    const float* bv = (const float*)d_in[8];
    const float* Wo = (const float*)d_in[9];
    const float* bo = (const float*)d_in[10];
    float* out = (float*)d_out;

    __half *gqh, *gkh, *gvh, *gWh, *gQ, *gK, *gV;
    cudaGetSymbolAddress((void**)&gqh, g_qh);
    cudaGetSymbolAddress((void**)&gkh, g_kh);
    cudaGetSymbolAddress((void**)&gvh, g_vh);
    cudaGetSymbolAddress((void**)&gWh, g_Wh4);
    cudaGetSymbolAddress((void**)&gQ, g_Q);
    cudaGetSymbolAddress((void**)&gK, g_K);
    cudaGetSymbolAddress((void**)&gV, g_V);

    const int write_extra = ((size_t)out_size >= OFF_Z + NZ) ? 1 : 0;

    cudaFuncSetAttribute(gemm_cp_kernel,
                         cudaFuncAttributeMaxDynamicSharedMemorySize, GEMM_SMEM);
    cudaFuncSetAttribute(gemm_out_fused_kernel,
                         cudaFuncAttributeMaxDynamicSharedMemorySize, FUSED_SMEM);
    cudaFuncSetAttribute(kv_reduce_f16_kernel,
                         cudaFuncAttributeMaxDynamicSharedMemorySize, KVT_SMEM);

    cvt_inputs_kernel<<<2048, 256>>>(q, k, v);
    cvt_weights_kernel<<<(DD * DD / 4 + 255) / 256, 256>>>(Wq, Wk, Wv, Wo);

    dim3 gemm_grid(DD / 256, MR / 128);     // (2, 256)
    gemm_cp_kernel<<<gemm_grid, 512, GEMM_SMEM>>>(gkh, gWh + (size_t)1 * DD * DD, bk, gK, 1);
    gemm_cp_kernel<<<gemm_grid, 512, GEMM_SMEM>>>(gvh, gWh + (size_t)2 * DD * DD, bv, gV, 0);
    gemm_cp_kernel<<<gemm_grid, 512, GEMM_SMEM>>>(gqh, gWh + (size_t)0 * DD * DD, bq, gQ, 1);

    dim3 kv_grid(BB * HH, KVC);             // (32, 32)
    kv_reduce_f16_kernel<<<kv_grid, 256, KVT_SMEM>>>(gK, gV);

    const int fin_total = NKV + NZ;
    kv_finalize_kernel<<<(fin_total + 255) / 256, 256>>>(out, write_extra);

    gemm_out_fused_kernel<<<gemm_grid, 512, FUSED_SMEM>>>(gQ, gWh + (size_t)3 * DD * DD, bo, out);
}

// round 15
// speedup vs baseline: 5.7378x; 1.1570x over previous
#include <cuda_runtime.h>
#include <cuda_fp16.h>
#include <cstdint>

// Problem constants
#define BB 4
#define SS 8192
#define DD 512
#define HH 8
#define DHD 64
#define MR (BB*SS)          // 32768 rows
#define EPSF 1e-6f
#define KVC 32

// Output layout: out [B,S,D], k_v [B,H,DH,DH], z [B,H,DH]
#define OFF_KV ((size_t)MR*DD)
#define NKV (BB*HH*DHD*DHD)
#define OFF_Z (OFF_KV + NKV)
#define NZ (BB*HH*DHD)

// Scratch (device globals)
__device__ __half g_qh[(size_t)MR*DD];   // fp16 inputs
__device__ __half g_kh[(size_t)MR*DD];
__device__ __half g_vh[(size_t)MR*DD];
__device__ __half g_Wh4[(size_t)4*DD*DD]; // fp16 weights: Wq,Wk,Wv,Wo
__device__ __half g_Q[(size_t)MR*DD];    // fp16 projected
__device__ __half g_K[(size_t)MR*DD];
__device__ __half g_V[(size_t)MR*DD];
__device__ __half g_att[(size_t)MR*DD];  // fp16 attention output
__device__ float g_kv_part[(size_t)KVC*BB*HH*DHD*DHD];
__device__ float g_z_part[(size_t)KVC*BB*HH*DHD];
__device__ __half g_kvT[NKV];
__device__ float g_z[NZ];

// ---------------------------------------------------------------------------
__device__ __forceinline__ void mma16816(float* c, const uint32_t* a, const uint32_t* b) {
    asm volatile(
        "mma.sync.aligned.m16n8k16.row.col.f32.f16.f16.f32 "
        "{%0,%1,%2,%3}, {%4,%5,%6,%7}, {%8,%9}, {%0,%1,%2,%3};\n"
        : "+f"(c[0]), "+f"(c[1]), "+f"(c[2]), "+f"(c[3])
        : "r"(a[0]), "r"(a[1]), "r"(a[2]), "r"(a[3]), "r"(b[0]), "r"(b[1]));
}

__device__ __forceinline__ void ldsm4(uint32_t* r, uint32_t addr) {
    asm volatile("ldmatrix.sync.aligned.m8n8.x4.shared.b16 {%0,%1,%2,%3}, [%4];"
        : "=r"(r[0]), "=r"(r[1]), "=r"(r[2]), "=r"(r[3]) : "r"(addr));
}

__device__ __forceinline__ void ldsm4t(uint32_t* r, uint32_t addr) {
    asm volatile("ldmatrix.sync.aligned.m8n8.x4.trans.shared.b16 {%0,%1,%2,%3}, [%4];"
        : "=r"(r[0]), "=r"(r[1]), "=r"(r[2]), "=r"(r[3]) : "r"(addr));
}

__device__ __forceinline__ void cpasync16(uint32_t saddr, const void* gptr) {
    asm volatile("cp.async.cg.shared.global [%0], [%1], 16;" :: "r"(saddr), "l"(gptr) : "memory");
}
#define CP_COMMIT() asm volatile("cp.async.commit_group;" ::: "memory")
#define CP_WAIT1()  asm volatile("cp.async.wait_group 1;" ::: "memory")

// ===========================================================================
// Conversion kernels
// ===========================================================================
__global__ void __launch_bounds__(256)
cvt_inputs_kernel(const float* __restrict__ q, const float* __restrict__ k,
                  const float* __restrict__ v)
{
    const size_t N4 = (size_t)MR * DD / 4;
    const size_t stride = (size_t)gridDim.x * blockDim.x;
    for (size_t i = (size_t)blockIdx.x * blockDim.x + threadIdx.x; i < N4; i += stride) {
        float4 a = ((const float4*)q)[i];
        float4 b = ((const float4*)k)[i];
        float4 c = ((const float4*)v)[i];
        __half2 r0 = __floats2half2_rn(a.x, a.y), r1 = __floats2half2_rn(a.z, a.w);
        ((uint2*)g_qh)[i] = make_uint2(*(uint32_t*)&r0, *(uint32_t*)&r1);
        r0 = __floats2half2_rn(b.x, b.y); r1 = __floats2half2_rn(b.z, b.w);
        ((uint2*)g_kh)[i] = make_uint2(*(uint32_t*)&r0, *(uint32_t*)&r1);
        r0 = __floats2half2_rn(c.x, c.y); r1 = __floats2half2_rn(c.z, c.w);
        ((uint2*)g_vh)[i] = make_uint2(*(uint32_t*)&r0, *(uint32_t*)&r1);
    }
}

__global__ void __launch_bounds__(256)
cvt_weights_kernel(const float* __restrict__ Wq, const float* __restrict__ Wk,
                   const float* __restrict__ Wv, const float* __restrict__ Wo)
{
    const int NW = DD * DD / 4;
    const int i = blockIdx.x * blockDim.x + threadIdx.x;
    const float* srcs[4] = {Wq, Wk, Wv, Wo};
    if (i < NW) {
#pragma unroll
        for (int w = 0; w < 4; w++) {
            float4 a = ((const float4*)srcs[w])[i];
            __half2 r0 = __floats2half2_rn(a.x, a.y), r1 = __floats2half2_rn(a.z, a.w);
            ((uint2*)(g_Wh4 + (size_t)w * DD * DD))[i] = make_uint2(*(uint32_t*)&r0, *(uint32_t*)&r1);
        }
    }
}

// ===========================================================================
// fp16 GEMM with cp.async 3-stage pipeline; fp16 or fp32 output.
// BM=128, BN=256, BK=32, 512 threads, warp tile 32x64.
// blockIdx.z selects among up to 3 fused problem instances.
// ===========================================================================
#define PADH 40
#define ROWB (PADH * 2)                 // 80 bytes per padded row
#define STG_B ((128 + 256) * ROWB)      // 30720 bytes per stage
#define GEMM_SMEM (3 * STG_B)           // 92160

__global__ void __launch_bounds__(512, 1)
gemm_cp_kernel(const __half* __restrict__ A0, const __half* __restrict__ W0,
               const float* __restrict__ b0p, __half* __restrict__ C0, int act0,
               const __half* __restrict__ A1, const __half* __restrict__ W1,
               const float* __restrict__ b1p, __half* __restrict__ C1, int act1,
               const __half* __restrict__ A2, const __half* __restrict__ W2,
               const float* __restrict__ b2p, __half* __restrict__ C2, int act2,
               float* __restrict__ Cf)    // if non-null (z==0 only), fp32 out
{
    extern __shared__ char smc[];
    const uint32_t sbase = (uint32_t)__cvta_generic_to_shared(smc);

    const int z = blockIdx.z;
    const __half* A = (z == 0) ? A0 : (z == 1) ? A1 : A2;
    const __half* W = (z == 0) ? W0 : (z == 1) ? W1 : W2;
    const float* bias = (z == 0) ? b0p : (z == 1) ? b1p : b2p;
    __half* C = (z == 0) ? C0 : (z == 1) ? C1 : C2;
    const int act = (z == 0) ? act0 : (z == 1) ? act1 : act2;

    const int tid  = threadIdx.x;
    const int lane = tid & 31;
    const int wid  = tid >> 5;
    const int wm   = wid & 3;
    const int wn   = wid >> 2;
    const int g    = lane >> 2;
    const int tq   = lane & 3;
    const int m0   = blockIdx.y * 128;
    const int n0   = blockIdx.x * 256;

    float acc[2][8][4];
#pragma unroll
    for (int i = 0; i < 2; i++)
#pragma unroll
        for (int j = 0; j < 8; j++)
#pragma unroll
            for (int c = 0; c < 4; c++) acc[i][j][c] = 0.f;

    const int ar = tid >> 2, ac = tid & 3;
    const int br0 = tid >> 2, bc0 = tid & 3;
    const int br1 = (tid + 512) >> 2, bc1 = (tid + 512) & 3;

    const __half* Ag = A + (size_t)m0 * DD;
    const __half* Wg = W + (size_t)n0 * DD;

    uint32_t aoff[2], boff[4];
#pragma unroll
    for (int mi = 0; mi < 2; mi++)
        aoff[mi] = (wm * 32 + mi * 16 + (lane & 15)) * PADH + ((lane >> 4) << 3);
#pragma unroll
    for (int pi = 0; pi < 4; pi++)
        boff[pi] = (128 + wn * 64 + pi * 16 + (lane & 7) + ((lane & 16) >> 1)) * PADH + (lane & 8);

#pragma unroll
    for (int p = 0; p < 2; p++) {
        const uint32_t st = sbase + p * STG_B;
        cpasync16(st + ar * ROWB + ac * 16, Ag + (size_t)ar * DD + p * 32 + ac * 8);
        cpasync16(st + 128 * ROWB + br0 * ROWB + bc0 * 16, Wg + (size_t)br0 * DD + p * 32 + bc0 * 8);
        cpasync16(st + 128 * ROWB + br1 * ROWB + bc1 * 16, Wg + (size_t)br1 * DD + p * 32 + bc1 * 8);
        CP_COMMIT();
    }

    int stage = 0;
    for (int kt = 0; kt < 16; kt++) {
        CP_WAIT1();
        __syncthreads();

        const uint32_t stg = sbase + stage * STG_B;
#pragma unroll
        for (int ks = 0; ks < 32; ks += 16) {
            uint32_t af[2][4], bf[8][2];
#pragma unroll
            for (int mi = 0; mi < 2; mi++)
                ldsm4(af[mi], stg + (aoff[mi] + ks) * 2);
#pragma unroll
            for (int pi = 0; pi < 4; pi++) {
                uint32_t r[4];
                ldsm4(r, stg + (boff[pi] + ks) * 2);
                bf[2 * pi][0] = r[0]; bf[2 * pi][1] = r[1];
                bf[2 * pi + 1][0] = r[2]; bf[2 * pi + 1][1] = r[3];
            }
#pragma unroll
            for (int mi = 0; mi < 2; mi++)
#pragma unroll
                for (int ni = 0; ni < 8; ni++)
                    mma16816(acc[mi][ni], af[mi], bf[ni]);
        }

        if (kt + 2 < 16) {
            const int ns = (stage + 2) % 3;
            const uint32_t st = sbase + ns * STG_B;
            const int kk = (kt + 2) * 32;
            cpasync16(st + ar * ROWB + ac * 16, Ag + (size_t)ar * DD + kk + ac * 8);
            cpasync16(st + 128 * ROWB + br0 * ROWB + bc0 * 16, Wg + (size_t)br0 * DD + kk + bc0 * 8);
            cpasync16(st + 128 * ROWB + br1 * ROWB + bc1 * 16, Wg + (size_t)br1 * DD + kk + bc1 * 8);
        }
        CP_COMMIT();
        stage = (stage + 1) % 3;
    }

    const bool f32out = (Cf != nullptr) && (z == 0);
#pragma unroll
    for (int mi = 0; mi < 2; mi++) {
        const int row = m0 + wm * 32 + mi * 16 + g;
#pragma unroll
        for (int ni = 0; ni < 8; ni++) {
            const int col = n0 + wn * 64 + ni * 8 + tq * 2;
            const float b0 = bias[col], b1 = bias[col + 1];
            float v0 = acc[mi][ni][0] + b0;
            float v1 = acc[mi][ni][1] + b1;
            float v2 = acc[mi][ni][2] + b0;
            float v3 = acc[mi][ni][3] + b1;
            if (act) {
                v0 = (v0 > 0.f) ? (v0 + 1.f) : __expf(v0);
                v1 = (v1 > 0.f) ? (v1 + 1.f) : __expf(v1);
                v2 = (v2 > 0.f) ? (v2 + 1.f) : __expf(v2);
                v3 = (v3 > 0.f) ? (v3 + 1.f) : __expf(v3);
            }
            if (f32out) {
                *(float2*)(Cf + (size_t)row * DD + col)       = make_float2(v0, v1);
                *(float2*)(Cf + (size_t)(row + 8) * DD + col) = make_float2(v2, v3);
            } else {
                *(__half2*)(C + (size_t)row * DD + col)       = __floats2half2_rn(v0, v1);
                *(__half2*)(C + (size_t)(row + 8) * DD + col) = __floats2half2_rn(v2, v3);
            }
        }
    }
}

// ===========================================================================
// KV reduce (fp16 mma.sync, trans ldmatrix)
// ===========================================================================
#define FPK 72
#define KVT_SMEM (2 * 256 * FPK * 2)

__global__ void __launch_bounds__(256)
kv_reduce_f16_kernel(const __half* __restrict__ Kmat, const __half* __restrict__ Vmat)
{
    extern __shared__ __half smk[];
    __half* Ks = smk;
    __half* Vs = smk + 256 * FPK;
    __shared__ float zred[4][DHD];
    const uint32_t sbase = (uint32_t)__cvta_generic_to_shared(smk);

    const int bh = blockIdx.x;
    const int chunk = blockIdx.y;
    const int b = bh / HH, h = bh % HH;
    const int s0g = chunk * 256;

    const __half* Kbase = Kmat + (size_t)b * SS * DD + (size_t)s0g * DD + h * DHD;
    const __half* Vbase = Vmat + (size_t)b * SS * DD + (size_t)s0g * DD + h * DHD;

    const int tid = threadIdx.x;
    const int lane = tid & 31;
    const int wid = tid >> 5;
    const int wm = wid & 1;
    const int wn = wid >> 1;
    const int g = lane >> 2;
    const int tq = lane & 3;

#pragma unroll
    for (int j = 0; j < 8; j++) {
        const int id = tid + 256 * j;
        const int row = id >> 3;
        const int c8 = (id & 7) * 8;
        *(uint4*)(Ks + row * FPK + c8) = *(const uint4*)(Kbase + (size_t)row * DD + c8);
        *(uint4*)(Vs + row * FPK + c8) = *(const uint4*)(Vbase + (size_t)row * DD + c8);
    }
    __syncthreads();

    uint32_t aoff[2];
#pragma unroll
    for (int mi = 0; mi < 2; mi++)
        aoff[mi] = (uint32_t)(256 * FPK)
                 + ((lane & 7) + ((lane & 16) >> 1)) * FPK
                 + (wm * 32 + mi * 16 + (lane & 8));
    const uint32_t boff = ((lane & 7) + (lane & 8)) * FPK
                        + (wn * 16 + ((lane & 16) >> 1));

    float acc[2][2][4];
#pragma unroll
    for (int i = 0; i < 2; i++)
#pragma unroll
        for (int j = 0; j < 2; j++)
#pragma unroll
            for (int c = 0; c < 4; c++) acc[i][j][c] = 0.f;

#pragma unroll 4
    for (int s = 0; s < 256; s += 16) {
        uint32_t af[2][4], bt[4];
#pragma unroll
        for (int mi = 0; mi < 2; mi++)
            ldsm4t(af[mi], sbase + (aoff[mi] + s * FPK) * 2);
        ldsm4t(bt, sbase + (boff + s * FPK) * 2);
        uint32_t bf0[2] = {bt[0], bt[1]};
        uint32_t bf1[2] = {bt[2], bt[3]};
#pragma unroll
        for (int mi = 0; mi < 2; mi++) {
            mma16816(acc[mi][0], af[mi], bf0);
            mma16816(acc[mi][1], af[mi], bf1);
        }
    }

    {
        const int dcol = tid & 63;
        const int part = tid >> 6;
        float zs = 0.f;
#pragma unroll 8
        for (int i = 0; i < 64; i++)
            zs += __half2float(Ks[(part * 64 + i) * FPK + dcol]);
        zred[part][dcol] = zs;
    }
    __syncthreads();
    if (tid < DHD)
        g_z_part[((size_t)chunk * (BB * HH) + bh) * DHD + tid] =
            zred[0][tid] + zred[1][tid] + zred[2][tid] + zred[3][tid];

    float* kvp = g_kv_part + ((size_t)chunk * (BB * HH) + bh) * DHD * DHD;
#pragma unroll
    for (int mi = 0; mi < 2; mi++) {
        const int m = wm * 32 + mi * 16 + g;
#pragma unroll
        for (int ni = 0; ni < 2; ni++) {
            const int d = wn * 16 + ni * 8 + tq * 2;
            *(float2*)&kvp[m * DHD + d]       = make_float2(acc[mi][ni][0], acc[mi][ni][1]);
            *(float2*)&kvp[(m + 8) * DHD + d] = make_float2(acc[mi][ni][2], acc[mi][ni][3]);
        }
    }
}

// ===========================================================================
// Finalize
// ===========================================================================
__global__ void __launch_bounds__(256)
kv_finalize_kernel(float* __restrict__ dout, int write_out)
{
    const int idx = blockIdx.x * blockDim.x + threadIdx.x;
    if (idx < NKV) {
        float s = 0.f;
#pragma unroll
        for (int c = 0; c < KVC; c++) s += g_kv_part[(size_t)c * NKV + idx];
        const int bh = idx >> 12;
        const int rem = idx & 4095;     // m*64 + d
        const int m = rem >> 6;
        const int d = rem & 63;
        g_kvT[bh * 4096 + rem] = __float2half(s);
        if (write_out) dout[OFF_KV + bh * 4096 + d * 64 + m] = s;
    } else if (idx < NKV + NZ) {
        const int id2 = idx - NKV;
        float s = 0.f;
#pragma unroll
        for (int c = 0; c < KVC; c++) s += g_z_part[(size_t)c * NZ + id2];
        g_z[id2] = s;
        if (write_out) dout[OFF_Z + id2] = s;
    }
}

// ===========================================================================
// Attention apply: att[s][h*64+m] = (Q_h[s,:] @ kv_h[:,m]) / (Q_h[s,:].z_h + eps)
// Per block: (bh, 128-row chunk). 256 threads, 8 warps x 16 rows.
// Output g_att laid out [b, s, h*64+m] (same as g_Q) for the output GEMM.
// ===========================================================================
#define FP 72

__global__ void __launch_bounds__(256, 2)
attn_apply_kernel(const __half* __restrict__ Q)
{
    __shared__ __half Qh[128 * FP];
    __shared__ __half KVh[64 * FP];
    __shared__ float zf[DHD];
    __shared__ float invden[128];
    const uint32_t sbase = (uint32_t)__cvta_generic_to_shared(Qh);
    const uint32_t kvbase = (uint32_t)__cvta_generic_to_shared(KVh);

    const int bh = blockIdx.x;
    const int chunk = blockIdx.y;
    const int b = bh / HH, h = bh % HH;
    const int m0 = chunk * 128;

    const int tid = threadIdx.x;
    const int lane = tid & 31;
    const int wid = tid >> 5;
    const int g = lane >> 2;
    const int tq = lane & 3;

    const __half* Qbase = Q + (size_t)b * SS * DD + (size_t)m0 * DD + h * DHD;

    // load Q tile [128][64]
#pragma unroll
    for (int j = 0; j < 4; j++) {
        const int id = tid + 256 * j;
        const int row = id >> 3;
        const int c8 = (id & 7) * 8;
        *(uint4*)(Qh + row * FP + c8) = *(const uint4*)(Qbase + (size_t)row * DD + c8);
    }
    // load kvT [64][64]
    {
        const uint32_t* src = (const uint32_t*)(g_kvT + (size_t)bh * 4096);
        uint32_t* dst = (uint32_t*)KVh;
#pragma unroll
        for (int j = 0; j < 8; j++) {
            const int w = tid + 256 * j;
            const int m = w >> 5;
            const int dw = w & 31;
            dst[m * (FP / 2) + dw] = src[w];
        }
    }
    if (tid < DHD) zf[tid] = g_z[bh * DHD + tid];
    __syncthreads();

    // den: 2 threads per row
    {
        const int r = tid >> 1;
        const int o = tid & 1;
        float s = 0.f;
        const __half2* qrow = (const __half2*)(Qh + r * FP) + o * 16;
#pragma unroll
        for (int i = 0; i < 16; i++) {
            float2 qf = __half22float2(qrow[i]);
            const int d = o * 32 + i * 2;
            s = fmaf(qf.x, zf[d], s);
            s = fmaf(qf.y, zf[d + 1], s);
        }
        s += __shfl_xor_sync(0xffffffffu, s, 1);
        if (o == 0) invden[r] = 1.0f / (s + EPSF);
    }
    __syncthreads();

    // mma: each warp 16 rows x 64 cols
    const uint32_t qoff = (wid * 16 + (lane & 15)) * FP + ((lane >> 4) << 3);
    uint32_t kvoff[4];
#pragma unroll
    for (int pi = 0; pi < 4; pi++)
        kvoff[pi] = (pi * 16 + (lane & 7) + ((lane & 16) >> 1)) * FP + (lane & 8);

    float aacc[8][4];
#pragma unroll
    for (int j = 0; j < 8; j++)
#pragma unroll
        for (int c = 0; c < 4; c++) aacc[j][c] = 0.f;

#pragma unroll
    for (int kt = 0; kt < 4; kt++) {
        uint32_t af[4], bf[8][2];
        ldsm4(af, sbase + (qoff + kt * 16) * 2);
#pragma unroll
        for (int pi = 0; pi < 4; pi++) {
            uint32_t r[4];
            ldsm4(r, kvbase + (kvoff[pi] + kt * 16) * 2);
            bf[2 * pi][0] = r[0]; bf[2 * pi][1] = r[1];
            bf[2 * pi + 1][0] = r[2]; bf[2 * pi + 1][1] = r[3];
        }
#pragma unroll
        for (int ni = 0; ni < 8; ni++)
            mma16816(aacc[ni], af, bf[ni]);
    }

    // scale + store to g_att [b][m0+r][h*64+col]
    __half* Obase = g_att + (size_t)b * SS * DD + (size_t)m0 * DD + h * DHD;
    const int r = wid * 16 + g;
    const float i0 = invden[r];
    const float i1 = invden[r + 8];
#pragma unroll
    for (int ni = 0; ni < 8; ni++) {
        const int col = ni * 8 + tq * 2;
        *(__half2*)(Obase + (size_t)r * DD + col) =
            __floats2half2_rn(aacc[ni][0] * i0, aacc[ni][1] * i0);
        *(__half2*)(Obase + (size_t)(r + 8) * DD + col) =
            __floats2half2_rn(aacc[ni][2] * i1, aacc[ni][3] * i1);
    }
}

// ===========================================================================
// Launch
// ===========================================================================
extern "C" void kernel_launch(void* const* d_in, const int* in_sizes, int n_in,
                              void* d_out, int out_size)
{
    const float* q  = (const float*)d_in[0];
    const float* k  = (const float*)d_in[1];
    const float* v  = (const float*)d_in[2];
    const float* Wq = (const float*)d_in[3];
    const float* bq = (const float*)d_in[4];
    const float* Wk = (const float*)d_in[5];
    const float* bk = (const float*)d_in[6];
    const float* Wv = (const float*)d_in[7];
    const float* bv = (const float*)d_in[8];
    const float* Wo = (const float*)d_in[9];
    const float* bo = (const float*)d_in[10];
    float* out = (float*)d_out;

    __half *gqh, *gkh, *gvh, *gWh, *gQ, *gK, *gV, *gA;
    cudaGetSymbolAddress((void**)&gqh, g_qh);
    cudaGetSymbolAddress((void**)&gkh, g_kh);
    cudaGetSymbolAddress((void**)&gvh, g_vh);
    cudaGetSymbolAddress((void**)&gWh, g_Wh4);
    cudaGetSymbolAddress((void**)&gQ, g_Q);
    cudaGetSymbolAddress((void**)&gK, g_K);
    cudaGetSymbolAddress((void**)&gV, g_V);
    cudaGetSymbolAddress((void**)&gA, g_att);

    const int write_extra = ((size_t)out_size >= OFF_Z + NZ) ? 1 : 0;

    cudaFuncSetAttribute(gemm_cp_kernel,
                         cudaFuncAttributeMaxDynamicSharedMemorySize, GEMM_SMEM);
    cudaFuncSetAttribute(kv_reduce_f16_kernel,
                         cudaFuncAttributeMaxDynamicSharedMemorySize, KVT_SMEM);

    cvt_inputs_kernel<<<2048, 256>>>(q, k, v);
    cvt_weights_kernel<<<(DD * DD / 4 + 255) / 256, 256>>>(Wq, Wk, Wv, Wo);

    // 3 input GEMMs fused into one launch (z = 0:K, 1:V, 2:Q)
    dim3 gemm3_grid(DD / 256, MR / 128, 3);
    gemm_cp_kernel<<<gemm3_grid, 512, GEMM_SMEM>>>(
        gkh, gWh + (size_t)1 * DD * DD, bk, gK, 1,
        gvh, gWh + (size_t)2 * DD * DD, bv, gV, 0,
        gqh, gWh + (size_t)0 * DD * DD, bq, gQ, 1,
        nullptr);

    dim3 kv_grid(BB * HH, KVC);
    kv_reduce_f16_kernel<<<kv_grid, 256, KVT_SMEM>>>(gK, gV);

    const int fin_total = NKV + NZ;
    kv_finalize_kernel<<<(fin_total + 255) / 256, 256>>>(out, write_extra);

    dim3 att_grid(BB * HH, SS / 128);
    attn_apply_kernel<<<att_grid, 256>>>(gQ);

    // Output GEMM: att @ Wo^T + bo -> fp32 out
    dim3 gemm1_grid(DD / 256, MR / 128, 1);
    gemm_cp_kernel<<<gemm1_grid, 512, GEMM_SMEM>>>(
        gA, gWh + (size_t)3 * DD * DD, bo, nullptr, 0,
        nullptr, nullptr, nullptr, nullptr, 0,
        nullptr, nullptr, nullptr, nullptr, 0,
        out);
}